// round 1
// baseline (speedup 1.0000x reference)
#include <cuda_runtime.h>
#include <math.h>

#define Bq 4
#define Sq 4096
#define Dq 256
#define Lq 6
#define Vq 32000
#define Hq 1024

// ---------------- scratch (no allocations allowed) ----------------
__device__ float g_ebuf[(size_t)Bq * Sq * Dq];   // e = ln(wte[tokens])        16MB
__device__ float g_p0buf[Sq * Dq];               // p_raw = ln(wpe[:S])         4MB
__device__ float g_hbuf[(size_t)Sq * Hq];        // FFN hidden                 16MB
__device__ float g_pbuf[Sq * Dq];                // p (post-FFN)                4MB
__device__ float g_mbuf[Lq * Dq];                // m_l = Wk (Wq^T p_last)
__device__ float g_sbuf[Lq * Sq];                // attention scores (last row)
__device__ float g_abuf[Lq * Sq];                // softmax weights
__device__ float g_ctxpart[32 * Lq * Bq * Dq];   // partial ctx over t-chunks
__device__ float g_ctx[Lq * Bq * Dq];            // ctx[l][b][d] = a_l @ e[b]
__device__ float g_attnout[Lq * Bq * Dq];        // ctx @ Wv per layer
__device__ float g_xhat[Bq * Dq];                // normalized last-token state

// ---------------- helpers ----------------
__device__ __forceinline__ float2 blockReduceSum2_256(float a, float b) {
    __shared__ float sa[8], sb[8];
    int lane = threadIdx.x & 31, w = threadIdx.x >> 5;
#pragma unroll
    for (int o = 16; o; o >>= 1) {
        a += __shfl_xor_sync(0xffffffffu, a, o);
        b += __shfl_xor_sync(0xffffffffu, b, o);
    }
    if (lane == 0) { sa[w] = a; sb[w] = b; }
    __syncthreads();
    if (w == 0) {
        a = (lane < 8) ? sa[lane] : 0.f;
        b = (lane < 8) ? sb[lane] : 0.f;
#pragma unroll
        for (int o = 4; o; o >>= 1) {
            a += __shfl_xor_sync(0xffffffffu, a, o);
            b += __shfl_xor_sync(0xffffffffu, b, o);
        }
        if (lane == 0) { sa[0] = a; sb[0] = b; }
    }
    __syncthreads();
    float ra = sa[0], rb = sb[0];
    __syncthreads();
    return make_float2(ra, rb);
}

// ---------------- K1: embedding + positional LN ----------------
// rows [0, B*S) -> e rows; rows [B*S, B*S+S) -> p_raw rows
__global__ void embed_ln_kernel(const int* __restrict__ tokens,
                                const float* __restrict__ wte,
                                const float* __restrict__ wpe,
                                const float* __restrict__ gew,
                                const float* __restrict__ gpw) {
    int row = blockIdx.x;
    int d = threadIdx.x;
    const float* src;
    float* dst;
    const float* g;
    if (row < Bq * Sq) {
        int tok = tokens[row];
        src = wte + (size_t)tok * Dq;
        dst = g_ebuf + (size_t)row * Dq;
        g = gew;
    } else {
        int s = row - Bq * Sq;
        src = wpe + (size_t)s * Dq;
        dst = g_p0buf + (size_t)s * Dq;
        g = gpw;
    }
    float x = src[d];
    float2 r = blockReduceSum2_256(x, x * x);
    float mean = r.x * (1.0f / Dq);
    float var = r.y * (1.0f / Dq) - mean * mean;
    dst[d] = (x - mean) * rsqrtf(var + 1e-5f) * g[d];
}

// ---------------- K2/K3: FFN GEMMs (fp32 tiled) ----------------
// MODE 0: h = gelu(p_raw @ ff_w1)     M=S, K=D, N=H
// MODE 1: p = p_raw + h @ ff_w2       M=S, K=H, N=D
template <int MODE>
__global__ void ffn_gemm(const float* __restrict__ W) {
    constexpr int Kd = (MODE == 0) ? Dq : Hq;
    constexpr int Nd = (MODE == 0) ? Hq : Dq;
    const float* __restrict__ A = (MODE == 0) ? g_p0buf : g_hbuf;
    float* __restrict__ C = (MODE == 0) ? g_hbuf : g_pbuf;

    __shared__ float As[16][68];
    __shared__ float Bs[16][68];

    int tid = threadIdx.x;
    int tx = tid & 15, ty = tid >> 4;
    int m0 = blockIdx.y * 64, n0 = blockIdx.x * 64;
    int arow = tid >> 2, acol = (tid & 3) * 4;
    int brow = tid >> 4, bcol = (tid & 15) * 4;

    float acc[4][4] = {};

    for (int k0 = 0; k0 < Kd; k0 += 16) {
        float4 av = *(const float4*)(A + (size_t)(m0 + arow) * Kd + k0 + acol);
        As[acol + 0][arow] = av.x;
        As[acol + 1][arow] = av.y;
        As[acol + 2][arow] = av.z;
        As[acol + 3][arow] = av.w;
        float4 bv = *(const float4*)(W + (size_t)(k0 + brow) * Nd + n0 + bcol);
        *(float4*)&Bs[brow][bcol] = bv;
        __syncthreads();
#pragma unroll
        for (int k = 0; k < 16; k++) {
            float4 aq = *(const float4*)&As[k][ty * 4];
            float4 bq = *(const float4*)&Bs[k][tx * 4];
            float a[4] = {aq.x, aq.y, aq.z, aq.w};
            float b[4] = {bq.x, bq.y, bq.z, bq.w};
#pragma unroll
            for (int i = 0; i < 4; i++)
#pragma unroll
                for (int j = 0; j < 4; j++) acc[i][j] += a[i] * b[j];
        }
        __syncthreads();
    }

#pragma unroll
    for (int i = 0; i < 4; i++) {
        int m = m0 + ty * 4 + i;
#pragma unroll
        for (int j = 0; j < 4; j++) {
            int n = n0 + tx * 4 + j;
            float v = acc[i][j];
            if (MODE == 0) {
                v = 0.5f * v * (1.0f + erff(v * 0.70710678118654752f));  // exact GELU
            } else {
                v += g_p0buf[(size_t)m * Nd + n];  // residual
            }
            C[(size_t)m * Nd + n] = v;
        }
    }
}

// ---------------- K4: m_l = Wk[l] @ (Wq[l]^T @ p_last) ----------------
__global__ void qkm_kernel(const float* __restrict__ Wq, const float* __restrict__ Wk) {
    int l = blockIdx.x;
    int j = threadIdx.x;  // 256 threads
    __shared__ float pl[Dq];
    __shared__ float q[Dq];
    pl[j] = g_pbuf[(size_t)(Sq - 1) * Dq + j];
    __syncthreads();
    const float* wq = Wq + (size_t)l * Dq * Dq;
    float acc = 0.f;
#pragma unroll 4
    for (int i = 0; i < Dq; i++) acc += pl[i] * wq[(size_t)i * Dq + j];
    q[j] = acc;
    __syncthreads();
    const float* wk = Wk + (size_t)l * Dq * Dq + (size_t)j * Dq;
    float m = 0.f;
#pragma unroll 4
    for (int jj = 0; jj < Dq; jj++) m += wk[jj] * q[jj];
    g_mbuf[l * Dq + j] = m;
}

// ---------------- K5: scores s[l][t] = (p[t] . m_l) / 16 ----------------
__global__ void score_kernel() {
    int l = blockIdx.y;
    int warp = threadIdx.x >> 5, lane = threadIdx.x & 31;
    int t = blockIdx.x * 8 + warp;
    const float* p = g_pbuf + (size_t)t * Dq;
    const float* m = g_mbuf + l * Dq;
    float acc = 0.f;
#pragma unroll
    for (int i = 0; i < 8; i++) {
        int d = lane + i * 32;
        acc += p[d] * m[d];
    }
#pragma unroll
    for (int o = 16; o; o >>= 1) acc += __shfl_xor_sync(0xffffffffu, acc, o);
    if (lane == 0) g_sbuf[l * Sq + t] = acc * 0.0625f;
}

// ---------------- K6: softmax per layer over S=4096 ----------------
__global__ void softmax_kernel() {
    int l = blockIdx.x;
    int tid = threadIdx.x;  // 1024 threads
    __shared__ float red[32];
    __shared__ float bc;
    float v[4];
    float mx = -1e30f;
#pragma unroll
    for (int i = 0; i < 4; i++) {
        v[i] = g_sbuf[l * Sq + tid + i * 1024];
        mx = fmaxf(mx, v[i]);
    }
#pragma unroll
    for (int o = 16; o; o >>= 1) mx = fmaxf(mx, __shfl_xor_sync(0xffffffffu, mx, o));
    if ((tid & 31) == 0) red[tid >> 5] = mx;
    __syncthreads();
    if (tid < 32) {
        float m = red[tid];
#pragma unroll
        for (int o = 16; o; o >>= 1) m = fmaxf(m, __shfl_xor_sync(0xffffffffu, m, o));
        if (tid == 0) bc = m;
    }
    __syncthreads();
    float M = bc;
    float sum = 0.f;
#pragma unroll
    for (int i = 0; i < 4; i++) {
        v[i] = expf(v[i] - M);
        sum += v[i];
    }
#pragma unroll
    for (int o = 16; o; o >>= 1) sum += __shfl_xor_sync(0xffffffffu, sum, o);
    __syncthreads();
    if ((tid & 31) == 0) red[tid >> 5] = sum;
    __syncthreads();
    if (tid < 32) {
        float s2 = red[tid];
#pragma unroll
        for (int o = 16; o; o >>= 1) s2 += __shfl_xor_sync(0xffffffffu, s2, o);
        if (tid == 0) bc = s2;
    }
    __syncthreads();
    float inv = 1.0f / bc;
#pragma unroll
    for (int i = 0; i < 4; i++) g_abuf[l * Sq + tid + i * 1024] = v[i] * inv;
}

// ---------------- K7: ctx partials — single pass over e for all 6 layers ----------------
__global__ void ctx_kernel() {
    int chunk = blockIdx.x;  // 32 chunks of 128 t
    int b = blockIdx.y;
    int d = threadIdx.x;
    __shared__ float as_[Lq][128];
    for (int i = d; i < Lq * 128; i += 256) {
        int l = i >> 7, t = i & 127;
        as_[l][t] = g_abuf[l * Sq + chunk * 128 + t];
    }
    __syncthreads();
    float acc[Lq] = {};
    const float* ep = g_ebuf + ((size_t)b * Sq + (size_t)chunk * 128) * Dq + d;
#pragma unroll 4
    for (int t = 0; t < 128; t++) {
        float ev = ep[(size_t)t * Dq];
#pragma unroll
        for (int l = 0; l < Lq; l++) acc[l] += as_[l][t] * ev;
    }
#pragma unroll
    for (int l = 0; l < Lq; l++)
        g_ctxpart[(((size_t)chunk * Lq + l) * Bq + b) * Dq + d] = acc[l];
}

// ---------------- K8: reduce ctx partials (fixed order => deterministic) ----------------
__global__ void ctx_reduce_kernel() {
    int l = blockIdx.x, b = blockIdx.y, d = threadIdx.x;
    float acc = 0.f;
#pragma unroll
    for (int c = 0; c < 32; c++)
        acc += g_ctxpart[(((size_t)c * Lq + l) * Bq + b) * Dq + d];
    g_ctx[((size_t)l * Bq + b) * Dq + d] = acc;
}

// ---------------- K9: attnout[l][b] = ctx[l][b] @ Wv[l] ----------------
__global__ void vproj_kernel(const float* __restrict__ Wv) {
    int l = blockIdx.x, b = blockIdx.y, d = threadIdx.x;
    __shared__ float c[Dq];
    c[d] = g_ctx[((size_t)l * Bq + b) * Dq + d];
    __syncthreads();
    const float* wv = Wv + (size_t)l * Dq * Dq;
    float acc = 0.f;
#pragma unroll 4
    for (int k = 0; k < Dq; k++) acc += c[k] * wv[(size_t)k * Dq + d];
    g_attnout[((size_t)l * Bq + b) * Dq + d] = acc;
}

// ---------------- K10: final residual sum + LN ----------------
__global__ void final_ln_kernel(const float* __restrict__ g_out_w) {
    int b = blockIdx.x, d = threadIdx.x;
    float x = g_ebuf[((size_t)b * Sq + Sq - 1) * Dq + d] + g_p0buf[(size_t)(Sq - 1) * Dq + d];
#pragma unroll
    for (int l = 0; l < Lq; l++) x += g_attnout[((size_t)l * Bq + b) * Dq + d];
    float2 r = blockReduceSum2_256(x, x * x);
    float mean = r.x * (1.0f / Dq);
    float var = r.y * (1.0f / Dq) - mean * mean;
    g_xhat[b * Dq + d] = (x - mean) * rsqrtf(var + 1e-5f) * g_out_w[d];
}

// ---------------- K11: logits = xhat @ ln(wte, g_e)^T ----------------
__global__ void logits_kernel(const float* __restrict__ wte,
                              const float* __restrict__ gew,
                              float* __restrict__ out) {
    __shared__ float xs[Bq * Dq];
    __shared__ float gs[Dq];
    int tid = threadIdx.x;
    for (int i = tid; i < Bq * Dq; i += 256) xs[i] = g_xhat[i];
    gs[tid] = gew[tid];
    __syncthreads();
    int warp = tid >> 5, lane = tid & 31;
    int v = blockIdx.x * 8 + warp;
    const float* w = wte + (size_t)v * Dq;
    float wv[8];
    float s = 0.f, ss = 0.f;
#pragma unroll
    for (int i = 0; i < 8; i++) {
        wv[i] = w[lane + i * 32];
        s += wv[i];
        ss += wv[i] * wv[i];
    }
#pragma unroll
    for (int o = 16; o; o >>= 1) {
        s += __shfl_xor_sync(0xffffffffu, s, o);
        ss += __shfl_xor_sync(0xffffffffu, ss, o);
    }
    float mean = s * (1.0f / Dq);
    float var = ss * (1.0f / Dq) - mean * mean;
    float rstd = rsqrtf(var + 1e-5f);
    float wn[8];
#pragma unroll
    for (int i = 0; i < 8; i++) wn[i] = (wv[i] - mean) * rstd * gs[lane + i * 32];
#pragma unroll
    for (int b = 0; b < Bq; b++) {
        float dot = 0.f;
#pragma unroll
        for (int i = 0; i < 8; i++) dot += wn[i] * xs[b * Dq + lane + i * 32];
#pragma unroll
        for (int o = 16; o; o >>= 1) dot += __shfl_xor_sync(0xffffffffu, dot, o);
        if (lane == 0) out[(size_t)b * Vq + v] = dot;
    }
}

// ---------------- launch ----------------
extern "C" void kernel_launch(void* const* d_in, const int* in_sizes, int n_in,
                              void* d_out, int out_size) {
    const int* tokens = (const int*)d_in[0];
    const float* wte = (const float*)d_in[1];
    const float* wpe = (const float*)d_in[2];
    const float* g_e = (const float*)d_in[3];
    const float* g_p = (const float*)d_in[4];
    const float* g_out = (const float*)d_in[5];
    const float* ff_w1 = (const float*)d_in[6];
    const float* ff_w2 = (const float*)d_in[7];
    const float* Wq = (const float*)d_in[8];
    const float* Wk = (const float*)d_in[9];
    const float* Wv = (const float*)d_in[10];
    float* out = (float*)d_out;

    // 1. embeddings + positional LN
    embed_ln_kernel<<<Bq * Sq + Sq, 256>>>(tokens, wte, wpe, g_e, g_p);
    // 2/3. FFN on p
    ffn_gemm<0><<<dim3(Hq / 64, Sq / 64), 256>>>(ff_w1);
    ffn_gemm<1><<<dim3(Dq / 64, Sq / 64), 256>>>(ff_w2);
    // 4. per-layer score direction m_l (all layers, one kernel)
    qkm_kernel<<<Lq, 256>>>(Wq, Wk);
    // 5. scores for the last query row
    score_kernel<<<dim3(Sq / 8, Lq), 256>>>();
    // 6. softmax per layer
    softmax_kernel<<<Lq, 1024>>>();
    // 7/8. ctx[l][b] = a_l @ e[b]  (single pass over e for all layers)
    ctx_kernel<<<dim3(32, Bq), 256>>>();
    ctx_reduce_kernel<<<dim3(Lq, Bq), 256>>>();
    // 9. project through Wv
    vproj_kernel<<<dim3(Lq, Bq), 256>>>(Wv);
    // 10. final LN
    final_ln_kernel<<<Bq, 256>>>(g_out);
    // 11. logits vs LN'd vocab table
    logits_kernel<<<Vq / 8, 256>>>(wte, g_e, out);
}

// round 2
// speedup vs baseline: 1.1578x; 1.1578x over previous
#include <cuda_runtime.h>
#include <math.h>

#define Bq 4
#define Sq 4096
#define Dq 256
#define Lq 6
#define Vq 32000
#define Hq 1024

// ---------------- scratch (no allocations allowed) ----------------
__device__ float g_ebuf[(size_t)Bq * Sq * Dq];   // e = ln(wte[tokens])        16MB
__device__ float g_p0buf[Sq * Dq];               // p_raw = ln(wpe[:S])         4MB
__device__ float g_hbuf[(size_t)Sq * Hq];        // FFN hidden                 16MB
__device__ float g_pbuf[Sq * Dq];                // p (post-FFN)                4MB
__device__ float g_qpart[Lq * 8 * Dq];           // partial q = Wq^T p_last
__device__ float g_mbuf[Lq * Dq];                // m_l = Wk (Wq^T p_last)
__device__ float g_sbuf[Lq * Sq];                // attention scores (last row)
__device__ float g_abuf[Lq * Sq];                // softmax weights
__device__ float g_ctxpart[32 * Lq * Bq * Dq];   // partial ctx over t-chunks
__device__ float g_ctx[Lq * Bq * Dq];            // ctx[l][b][d] = a_l @ e[b]
__device__ float g_attnout[Lq * Bq * Dq];        // ctx @ Wv per layer
__device__ float g_xhat[Bq * Dq];                // normalized last-token state

// ---------------- helpers ----------------
__device__ __forceinline__ float2 blockReduceSum2_256(float a, float b) {
    __shared__ float sa[8], sb[8];
    int lane = threadIdx.x & 31, w = threadIdx.x >> 5;
#pragma unroll
    for (int o = 16; o; o >>= 1) {
        a += __shfl_xor_sync(0xffffffffu, a, o);
        b += __shfl_xor_sync(0xffffffffu, b, o);
    }
    if (lane == 0) { sa[w] = a; sb[w] = b; }
    __syncthreads();
    if (w == 0) {
        a = (lane < 8) ? sa[lane] : 0.f;
        b = (lane < 8) ? sb[lane] : 0.f;
#pragma unroll
        for (int o = 4; o; o >>= 1) {
            a += __shfl_xor_sync(0xffffffffu, a, o);
            b += __shfl_xor_sync(0xffffffffu, b, o);
        }
        if (lane == 0) { sa[0] = a; sb[0] = b; }
    }
    __syncthreads();
    float ra = sa[0], rb = sb[0];
    __syncthreads();
    return make_float2(ra, rb);
}

// ---------------- K1: embedding + positional LN ----------------
__global__ void embed_ln_kernel(const int* __restrict__ tokens,
                                const float* __restrict__ wte,
                                const float* __restrict__ wpe,
                                const float* __restrict__ gew,
                                const float* __restrict__ gpw) {
    int row = blockIdx.x;
    int d = threadIdx.x;
    const float* src;
    float* dst;
    const float* g;
    if (row < Bq * Sq) {
        int tok = tokens[row];
        src = wte + (size_t)tok * Dq;
        dst = g_ebuf + (size_t)row * Dq;
        g = gew;
    } else {
        int s = row - Bq * Sq;
        src = wpe + (size_t)s * Dq;
        dst = g_p0buf + (size_t)s * Dq;
        g = gpw;
    }
    float x = src[d];
    float2 r = blockReduceSum2_256(x, x * x);
    float mean = r.x * (1.0f / Dq);
    float var = r.y * (1.0f / Dq) - mean * mean;
    dst[d] = (x - mean) * rsqrtf(var + 1e-5f) * g[d];
}

// ---------------- K2/K3: FFN GEMMs (fp32, 128x64 tile, 8x4 per thread) ----
// MODE 0: h = gelu(p_raw @ ff_w1)     M=S, K=D, N=H
// MODE 1: p = p_raw + h @ ff_w2       M=S, K=H, N=D
template <int MODE>
__global__ void __launch_bounds__(256, 2) ffn_gemm(const float* __restrict__ W) {
    constexpr int Kd = (MODE == 0) ? Dq : Hq;
    constexpr int Nd = (MODE == 0) ? Hq : Dq;
    constexpr int BM = 128, BN = 64, BK = 16;
    const float* __restrict__ A = (MODE == 0) ? g_p0buf : g_hbuf;
    float* __restrict__ C = (MODE == 0) ? g_hbuf : g_pbuf;

    __shared__ float As[BK][BM + 4];   // transposed: As[k][m]
    __shared__ float Bs[BK][BN + 4];

    int tid = threadIdx.x;
    int tx = tid & 15, ty = tid >> 4;          // 16x16 threads
    int m0 = blockIdx.y * BM, n0 = blockIdx.x * BN;

    // A load mapping: 128x16 = 512 float4; 2 per thread
    int aidx0 = tid * 2;
    // B load mapping: 16x64 = 256 float4; 1 per thread
    int brow = tid >> 4, bcol4 = (tid & 15);

    float acc[8][4] = {};

    for (int k0 = 0; k0 < Kd; k0 += BK) {
#pragma unroll
        for (int i = 0; i < 2; i++) {
            int idx = aidx0 + i;
            int ar = idx >> 2;             // row in tile 0..127
            int ac4 = (idx & 3) * 4;       // k-col 0,4,8,12
            float4 av = *(const float4*)(A + (size_t)(m0 + ar) * Kd + k0 + ac4);
            As[ac4 + 0][ar] = av.x;
            As[ac4 + 1][ar] = av.y;
            As[ac4 + 2][ar] = av.z;
            As[ac4 + 3][ar] = av.w;
        }
        {
            float4 bv = *(const float4*)(W + (size_t)(k0 + brow) * Nd + n0 + bcol4 * 4);
            *(float4*)&Bs[brow][bcol4 * 4] = bv;
        }
        __syncthreads();
#pragma unroll
        for (int k = 0; k < BK; k++) {
            float a[8], b[4];
            float4 a0 = *(const float4*)&As[k][ty * 8];
            float4 a1 = *(const float4*)&As[k][ty * 8 + 4];
            a[0] = a0.x; a[1] = a0.y; a[2] = a0.z; a[3] = a0.w;
            a[4] = a1.x; a[5] = a1.y; a[6] = a1.z; a[7] = a1.w;
            float4 b0 = *(const float4*)&Bs[k][tx * 4];
            b[0] = b0.x; b[1] = b0.y; b[2] = b0.z; b[3] = b0.w;
#pragma unroll
            for (int i = 0; i < 8; i++)
#pragma unroll
                for (int j = 0; j < 4; j++) acc[i][j] += a[i] * b[j];
        }
        __syncthreads();
    }

#pragma unroll
    for (int i = 0; i < 8; i++) {
        int m = m0 + ty * 8 + i;
#pragma unroll
        for (int j = 0; j < 4; j++) {
            int n = n0 + tx * 4 + j;
            float v = acc[i][j];
            if (MODE == 0) {
                v = 0.5f * v * (1.0f + erff(v * 0.70710678118654752f));  // exact GELU
            } else {
                v += g_p0buf[(size_t)m * Nd + n];  // residual
            }
            C[(size_t)m * Nd + n] = v;
        }
    }
}

// ---------------- K4a: partial q = Wq^T p_last (split K into 8 chunks) ----
__global__ void qk_q_kernel(const float* __restrict__ Wq) {
    int l = blockIdx.x, c = blockIdx.y;
    int j = threadIdx.x;
    __shared__ float pl[32];
    if (j < 32) pl[j] = g_pbuf[(size_t)(Sq - 1) * Dq + c * 32 + j];
    __syncthreads();
    const float* wq = Wq + (size_t)l * Dq * Dq + (size_t)c * 32 * Dq;
    float acc = 0.f;
#pragma unroll
    for (int i = 0; i < 32; i++) acc += pl[i] * wq[(size_t)i * Dq + j];
    g_qpart[(l * 8 + c) * Dq + j] = acc;
}

// ---------------- K4b: m_l = Wk_l @ q_l (warp per output row) ----------
__global__ void qk_m_kernel(const float* __restrict__ Wk) {
    int l = blockIdx.x;
    int tid = threadIdx.x;            // 256 threads, 8 warps
    int warp = tid >> 5, lane = tid & 31;
    __shared__ float qs[Dq];
    {
        float acc = 0.f;
#pragma unroll
        for (int c = 0; c < 8; c++) acc += g_qpart[(l * 8 + c) * Dq + tid];
        qs[tid] = acc;
    }
    __syncthreads();
    int j = blockIdx.y * 8 + warp;
    const float* wk = Wk + (size_t)l * Dq * Dq + (size_t)j * Dq;
    float m = 0.f;
#pragma unroll
    for (int i = 0; i < 8; i++) {
        int idx = lane + i * 32;
        m += wk[idx] * qs[idx];
    }
#pragma unroll
    for (int o = 16; o; o >>= 1) m += __shfl_xor_sync(0xffffffffu, m, o);
    if (lane == 0) g_mbuf[l * Dq + j] = m;
}

// ---------------- K5: scores s[l][t] = (p[t] . m_l) / 16 ----------------
__global__ void score_kernel() {
    int l = blockIdx.y;
    int warp = threadIdx.x >> 5, lane = threadIdx.x & 31;
    int t = blockIdx.x * 8 + warp;
    const float* p = g_pbuf + (size_t)t * Dq;
    const float* m = g_mbuf + l * Dq;
    float acc = 0.f;
#pragma unroll
    for (int i = 0; i < 8; i++) {
        int d = lane + i * 32;
        acc += p[d] * m[d];
    }
#pragma unroll
    for (int o = 16; o; o >>= 1) acc += __shfl_xor_sync(0xffffffffu, acc, o);
    if (lane == 0) g_sbuf[l * Sq + t] = acc * 0.0625f;
}

// ---------------- K6: softmax per layer over S=4096 ----------------
__global__ void softmax_kernel() {
    int l = blockIdx.x;
    int tid = threadIdx.x;  // 1024 threads
    __shared__ float red[32];
    __shared__ float bc;
    float v[4];
    float mx = -1e30f;
#pragma unroll
    for (int i = 0; i < 4; i++) {
        v[i] = g_sbuf[l * Sq + tid + i * 1024];
        mx = fmaxf(mx, v[i]);
    }
#pragma unroll
    for (int o = 16; o; o >>= 1) mx = fmaxf(mx, __shfl_xor_sync(0xffffffffu, mx, o));
    if ((tid & 31) == 0) red[tid >> 5] = mx;
    __syncthreads();
    if (tid < 32) {
        float m = red[tid];
#pragma unroll
        for (int o = 16; o; o >>= 1) m = fmaxf(m, __shfl_xor_sync(0xffffffffu, m, o));
        if (tid == 0) bc = m;
    }
    __syncthreads();
    float M = bc;
    float sum = 0.f;
#pragma unroll
    for (int i = 0; i < 4; i++) {
        v[i] = expf(v[i] - M);
        sum += v[i];
    }
#pragma unroll
    for (int o = 16; o; o >>= 1) sum += __shfl_xor_sync(0xffffffffu, sum, o);
    __syncthreads();
    if ((tid & 31) == 0) red[tid >> 5] = sum;
    __syncthreads();
    if (tid < 32) {
        float s2 = red[tid];
#pragma unroll
        for (int o = 16; o; o >>= 1) s2 += __shfl_xor_sync(0xffffffffu, s2, o);
        if (tid == 0) bc = s2;
    }
    __syncthreads();
    float inv = 1.0f / bc;
#pragma unroll
    for (int i = 0; i < 4; i++) g_abuf[l * Sq + tid + i * 1024] = v[i] * inv;
}

// ---------------- K7: ctx partials — single pass over e for all 6 layers --
__global__ void ctx_kernel() {
    int chunk = blockIdx.x;  // 32 chunks of 128 t
    int b = blockIdx.y;
    int d = threadIdx.x;
    __shared__ float as_[Lq][128];
    for (int i = d; i < Lq * 128; i += 256) {
        int l = i >> 7, t = i & 127;
        as_[l][t] = g_abuf[l * Sq + chunk * 128 + t];
    }
    __syncthreads();
    float acc[Lq] = {};
    const float* ep = g_ebuf + ((size_t)b * Sq + (size_t)chunk * 128) * Dq + d;
#pragma unroll 4
    for (int t = 0; t < 128; t++) {
        float ev = ep[(size_t)t * Dq];
#pragma unroll
        for (int l = 0; l < Lq; l++) acc[l] += as_[l][t] * ev;
    }
#pragma unroll
    for (int l = 0; l < Lq; l++)
        g_ctxpart[(((size_t)chunk * Lq + l) * Bq + b) * Dq + d] = acc[l];
}

// ---------------- K8: reduce ctx partials (fixed order => deterministic) --
__global__ void ctx_reduce_kernel() {
    int l = blockIdx.x, b = blockIdx.y, d = threadIdx.x;
    float acc = 0.f;
#pragma unroll
    for (int c = 0; c < 32; c++)
        acc += g_ctxpart[(((size_t)c * Lq + l) * Bq + b) * Dq + d];
    g_ctx[((size_t)l * Bq + b) * Dq + d] = acc;
}

// ---------------- K9: attnout[l][b] = ctx[l][b] @ Wv[l] ----------------
__global__ void vproj_kernel(const float* __restrict__ Wv) {
    int l = blockIdx.x, b = blockIdx.y, d = threadIdx.x;
    __shared__ float c[Dq];
    c[d] = g_ctx[((size_t)l * Bq + b) * Dq + d];
    __syncthreads();
    const float* wv = Wv + (size_t)l * Dq * Dq;
    float acc = 0.f;
#pragma unroll 4
    for (int k = 0; k < Dq; k++) acc += c[k] * wv[(size_t)k * Dq + d];
    g_attnout[((size_t)l * Bq + b) * Dq + d] = acc;
}

// ---------------- K10: final residual sum + LN ----------------
__global__ void final_ln_kernel(const float* __restrict__ g_out_w) {
    int b = blockIdx.x, d = threadIdx.x;
    float x = g_ebuf[((size_t)b * Sq + Sq - 1) * Dq + d] + g_p0buf[(size_t)(Sq - 1) * Dq + d];
#pragma unroll
    for (int l = 0; l < Lq; l++) x += g_attnout[((size_t)l * Bq + b) * Dq + d];
    float2 r = blockReduceSum2_256(x, x * x);
    float mean = r.x * (1.0f / Dq);
    float var = r.y * (1.0f / Dq) - mean * mean;
    g_xhat[b * Dq + d] = (x - mean) * rsqrtf(var + 1e-5f) * g_out_w[d];
}

// ---------------- K11: logits = xhat @ ln(wte, g_e)^T ----------------
__global__ void logits_kernel(const float* __restrict__ wte,
                              const float* __restrict__ gew,
                              float* __restrict__ out) {
    __shared__ float xs[Bq * Dq];
    __shared__ float gs[Dq];
    int tid = threadIdx.x;
    for (int i = tid; i < Bq * Dq; i += 256) xs[i] = g_xhat[i];
    gs[tid] = gew[tid];
    __syncthreads();
    int warp = tid >> 5, lane = tid & 31;
    int v = blockIdx.x * 8 + warp;
    const float* w = wte + (size_t)v * Dq;
    float wv[8];
    float s = 0.f, ss = 0.f;
#pragma unroll
    for (int i = 0; i < 8; i++) {
        wv[i] = w[lane + i * 32];
        s += wv[i];
        ss += wv[i] * wv[i];
    }
#pragma unroll
    for (int o = 16; o; o >>= 1) {
        s += __shfl_xor_sync(0xffffffffu, s, o);
        ss += __shfl_xor_sync(0xffffffffu, ss, o);
    }
    float mean = s * (1.0f / Dq);
    float var = ss * (1.0f / Dq) - mean * mean;
    float rstd = rsqrtf(var + 1e-5f);
    float wn[8];
#pragma unroll
    for (int i = 0; i < 8; i++) wn[i] = (wv[i] - mean) * rstd * gs[lane + i * 32];
#pragma unroll
    for (int b = 0; b < Bq; b++) {
        float dot = 0.f;
#pragma unroll
        for (int i = 0; i < 8; i++) dot += wn[i] * xs[b * Dq + lane + i * 32];
#pragma unroll
        for (int o = 16; o; o >>= 1) dot += __shfl_xor_sync(0xffffffffu, dot, o);
        if (lane == 0) out[(size_t)b * Vq + v] = dot;
    }
}

// ---------------- launch ----------------
extern "C" void kernel_launch(void* const* d_in, const int* in_sizes, int n_in,
                              void* d_out, int out_size) {
    const int* tokens = (const int*)d_in[0];
    const float* wte = (const float*)d_in[1];
    const float* wpe = (const float*)d_in[2];
    const float* g_e = (const float*)d_in[3];
    const float* g_p = (const float*)d_in[4];
    const float* g_out = (const float*)d_in[5];
    const float* ff_w1 = (const float*)d_in[6];
    const float* ff_w2 = (const float*)d_in[7];
    const float* Wq = (const float*)d_in[8];
    const float* Wk = (const float*)d_in[9];
    const float* Wv = (const float*)d_in[10];
    float* out = (float*)d_out;

    // 1. embeddings + positional LN
    embed_ln_kernel<<<Bq * Sq + Sq, 256>>>(tokens, wte, wpe, g_e, g_p);
    // 2/3. FFN on p
    ffn_gemm<0><<<dim3(Hq / 64, Sq / 128), 256>>>(ff_w1);
    ffn_gemm<1><<<dim3(Dq / 64, Sq / 128), 256>>>(ff_w2);
    // 4. per-layer score direction m_l (parallelized)
    qk_q_kernel<<<dim3(Lq, 8), 256>>>(Wq);
    qk_m_kernel<<<dim3(Lq, 32), 256>>>(Wk);
    // 5. scores for the last query row
    score_kernel<<<dim3(Sq / 8, Lq), 256>>>();
    // 6. softmax per layer
    softmax_kernel<<<Lq, 1024>>>();
    // 7/8. ctx[l][b] = a_l @ e[b]  (single pass over e for all layers)
    ctx_kernel<<<dim3(32, Bq), 256>>>();
    ctx_reduce_kernel<<<dim3(Lq, Bq), 256>>>();
    // 9. project through Wv
    vproj_kernel<<<dim3(Lq, Bq), 256>>>(Wv);
    // 10. final LN
    final_ln_kernel<<<Bq, 256>>>(g_out);
    // 11. logits vs LN'd vocab table
    logits_kernel<<<Vq / 8, 256>>>(wte, g_e, out);
}

// round 4
// speedup vs baseline: 2.2101x; 1.9089x over previous
#include <cuda_runtime.h>
#include <cuda_bf16.h>
#include <math.h>
#include <stdint.h>

#define Bq 4
#define Sq 4096
#define Dq 256
#define Lq 6
#define Vq 32000
#define Hq 1024

// ---------------- scratch (no allocations allowed) ----------------
__device__ float g_ebuf[(size_t)Bq * Sq * Dq];   // e = ln(wte[tokens])        16MB
__device__ float g_p0buf[Sq * Dq];               // p_raw = ln(wpe[:S])         4MB
__device__ float g_pbuf[Sq * Dq];                // p (post-FFN, fp32)          4MB
__device__ __nv_bfloat16 g_pA[Sq * Dq];          // bf16(p_raw)                 2MB
__device__ __nv_bfloat16 g_hbf[(size_t)Sq * Hq]; // bf16 FFN hidden             8MB
__device__ __nv_bfloat16 g_w1t[Hq * Dq];         // ff_w1^T  [H][D] bf16
__device__ __nv_bfloat16 g_w2t[Dq * Hq];         // ff_w2^T  [D][H] bf16
__device__ float g_qpart[Lq * 8 * Dq];
__device__ float g_mbuf[Lq * Dq];
__device__ float g_sbuf[Lq * Sq];
__device__ float g_abuf[Lq * Sq];
__device__ float g_ctxpart[32 * Lq * Bq * Dq];
__device__ float g_ctx[Lq * Bq * Dq];
__device__ float g_attnout[Lq * Bq * Dq];
__device__ float g_xhat[Bq * Dq];

// ---------------- helpers ----------------
__device__ __forceinline__ uint32_t smem_u32(const void* p) {
    uint32_t a;
    asm("{ .reg .u64 t; cvta.to.shared.u64 t, %1; cvt.u32.u64 %0, t; }" : "=r"(a) : "l"(p));
    return a;
}

__device__ __forceinline__ void ldsm_x4(uint32_t* r, uint32_t addr) {
    asm volatile("ldmatrix.sync.aligned.m8n8.x4.shared.b16 {%0,%1,%2,%3}, [%4];"
                 : "=r"(r[0]), "=r"(r[1]), "=r"(r[2]), "=r"(r[3]) : "r"(addr));
}

__device__ __forceinline__ void mma_bf16(float* c, const uint32_t* a, const uint32_t* b) {
    asm volatile(
        "mma.sync.aligned.m16n8k16.row.col.f32.bf16.bf16.f32 "
        "{%0,%1,%2,%3}, {%4,%5,%6,%7}, {%8,%9}, {%0,%1,%2,%3};"
        : "+f"(c[0]), "+f"(c[1]), "+f"(c[2]), "+f"(c[3])
        : "r"(a[0]), "r"(a[1]), "r"(a[2]), "r"(a[3]), "r"(b[0]), "r"(b[1]));
}

__device__ __forceinline__ float2 blockReduceSum2_256(float a, float b) {
    __shared__ float sa[8], sb[8];
    int lane = threadIdx.x & 31, w = threadIdx.x >> 5;
#pragma unroll
    for (int o = 16; o; o >>= 1) {
        a += __shfl_xor_sync(0xffffffffu, a, o);
        b += __shfl_xor_sync(0xffffffffu, b, o);
    }
    if (lane == 0) { sa[w] = a; sb[w] = b; }
    __syncthreads();
    if (w == 0) {
        a = (lane < 8) ? sa[lane] : 0.f;
        b = (lane < 8) ? sb[lane] : 0.f;
#pragma unroll
        for (int o = 4; o; o >>= 1) {
            a += __shfl_xor_sync(0xffffffffu, a, o);
            b += __shfl_xor_sync(0xffffffffu, b, o);
        }
        if (lane == 0) { sa[0] = a; sb[0] = b; }
    }
    __syncthreads();
    float ra = sa[0], rb = sb[0];
    __syncthreads();
    return make_float2(ra, rb);
}

// ---------------- K1: embedding + positional LN ----------------
__global__ void embed_ln_kernel(const int* __restrict__ tokens,
                                const float* __restrict__ wte,
                                const float* __restrict__ wpe,
                                const float* __restrict__ gew,
                                const float* __restrict__ gpw) {
    int row = blockIdx.x;
    int d = threadIdx.x;
    const float* src;
    float* dst;
    const float* g;
    if (row < Bq * Sq) {
        int tok = tokens[row];
        src = wte + (size_t)tok * Dq;
        dst = g_ebuf + (size_t)row * Dq;
        g = gew;
    } else {
        int s = row - Bq * Sq;
        src = wpe + (size_t)s * Dq;
        dst = g_p0buf + (size_t)s * Dq;
        g = gpw;
    }
    float x = src[d];
    float2 r = blockReduceSum2_256(x, x * x);
    float mean = r.x * (1.0f / Dq);
    float var = r.y * (1.0f / Dq) - mean * mean;
    dst[d] = (x - mean) * rsqrtf(var + 1e-5f) * g[d];
}

// ---------------- prep: fp32 -> bf16 convert ----------------
__global__ void conv_bf16_kernel(const float* __restrict__ src, __nv_bfloat16* __restrict__ dst) {
    int i = blockIdx.x * 256 + threadIdx.x;  // float4 index
    float4 v = ((const float4*)src)[i];
    __nv_bfloat162 lo = __floats2bfloat162_rn(v.x, v.y);
    __nv_bfloat162 hi = __floats2bfloat162_rn(v.z, v.w);
    uint2 u;
    u.x = reinterpret_cast<uint32_t&>(lo);
    u.y = reinterpret_cast<uint32_t&>(hi);
    ((uint2*)dst)[i] = u;
}

// ---------------- prep: transpose fp32 [R][C] -> bf16 [C][R] ----------------
__global__ void transpose_bf16_kernel(const float* __restrict__ src,
                                      __nv_bfloat16* __restrict__ dst, int R, int C) {
    __shared__ float t[32][33];
    int c0 = blockIdx.x * 32, r0 = blockIdx.y * 32;
    int x = threadIdx.x, y = threadIdx.y;  // 32 x 8
#pragma unroll
    for (int i = 0; i < 32; i += 8) t[y + i][x] = src[(size_t)(r0 + y + i) * C + c0 + x];
    __syncthreads();
#pragma unroll
    for (int i = 0; i < 32; i += 8)
        dst[(size_t)(c0 + y + i) * R + r0 + x] = __float2bfloat16(t[x][y + i]);
}

// ---------------- FFN GEMMs via mma.sync (bf16 HMMA, fp32 accum) ----------
// MODE 0: h = gelu(p_raw @ ff_w1), K=256,  N=1024, out bf16 g_hbf
// MODE 1: p = p_raw + h @ ff_w2,   K=1024, N=256,  out fp32 g_pbuf
// CTA tile 128x64, BK=64; 8 warps (4 m x 2 n), warp tile 32x32.
template <int MODE>
__global__ void __launch_bounds__(256) ffn_mma_kernel() {
    constexpr int Kd = (MODE == 0) ? Dq : Hq;
    constexpr int Nd = (MODE == 0) ? Hq : Dq;
    constexpr int BK = 64, LDS = BK + 8;  // bf16 elems per smem row (144B stride)
    const __nv_bfloat16* __restrict__ A = (MODE == 0) ? g_pA : g_hbf;
    const __nv_bfloat16* __restrict__ Bt = (MODE == 0) ? g_w1t : g_w2t;

    __shared__ __nv_bfloat16 As[128][LDS];
    __shared__ __nv_bfloat16 Bs[64][LDS];

    int tid = threadIdx.x, wid = tid >> 5, lane = tid & 31;
    int warp_m = wid & 3, warp_n = wid >> 2;
    int m0 = blockIdx.y * 128, n0 = blockIdx.x * 64;

    // ldmatrix lane address components
    int a_row = warp_m * 32 + ((lane >> 3) & 1) * 8 + (lane & 7);
    int a_col = (lane >> 4) * 8;
    int b_row = warp_n * 32 + ((lane >> 4) & 1) * 8 + (lane & 7);
    int b_col = ((lane >> 3) & 1) * 8;
    uint32_t As_base = smem_u32(&As[0][0]);
    uint32_t Bs_base = smem_u32(&Bs[0][0]);

    float c[2][4][4] = {};  // [mt][nt][frag]

    for (int k0 = 0; k0 < Kd; k0 += BK) {
        // load A: 128 x 64 bf16
#pragma unroll
        for (int i = 0; i < 4; i++) {
            int idx = tid + i * 256;
            int r = idx >> 3, cc = (idx & 7) * 8;
            *(uint4*)&As[r][cc] = *(const uint4*)(A + (size_t)(m0 + r) * Kd + k0 + cc);
        }
        // load B: 64 x 64 bf16 (Bt is [N][K])
#pragma unroll
        for (int i = 0; i < 2; i++) {
            int idx = tid + i * 256;
            int r = idx >> 3, cc = (idx & 7) * 8;
            *(uint4*)&Bs[r][cc] = *(const uint4*)(Bt + (size_t)(n0 + r) * Kd + k0 + cc);
        }
        __syncthreads();
#pragma unroll
        for (int kk = 0; kk < BK / 16; kk++) {
            uint32_t a[2][4], b[2][4];
#pragma unroll
            for (int mt = 0; mt < 2; mt++) {
                uint32_t addr = As_base + ((a_row + mt * 16) * LDS + kk * 16 + a_col) * 2;
                ldsm_x4(a[mt], addr);
            }
#pragma unroll
            for (int nt2 = 0; nt2 < 2; nt2++) {
                uint32_t addr = Bs_base + ((b_row + nt2 * 16) * LDS + kk * 16 + b_col) * 2;
                ldsm_x4(b[nt2], addr);
            }
#pragma unroll
            for (int mt = 0; mt < 2; mt++)
#pragma unroll
                for (int nt2 = 0; nt2 < 2; nt2++) {
                    mma_bf16(c[mt][nt2 * 2 + 0], a[mt], &b[nt2][0]);
                    mma_bf16(c[mt][nt2 * 2 + 1], a[mt], &b[nt2][2]);
                }
        }
        __syncthreads();
    }

    // epilogue
    int group = lane >> 2, tg = lane & 3;
#pragma unroll
    for (int mt = 0; mt < 2; mt++) {
#pragma unroll
        for (int nt = 0; nt < 4; nt++) {
#pragma unroll
            for (int half = 0; half < 2; half++) {
                int m = m0 + warp_m * 32 + mt * 16 + group + half * 8;
                int n = n0 + warp_n * 32 + nt * 8 + tg * 2;
                float v0 = c[mt][nt][half * 2 + 0];
                float v1 = c[mt][nt][half * 2 + 1];
                if (MODE == 0) {
                    v0 = 0.5f * v0 * (1.0f + erff(v0 * 0.70710678118654752f));
                    v1 = 0.5f * v1 * (1.0f + erff(v1 * 0.70710678118654752f));
                    __nv_bfloat162 h = __floats2bfloat162_rn(v0, v1);
                    *(uint32_t*)&g_hbf[(size_t)m * Nd + n] = reinterpret_cast<uint32_t&>(h);
                } else {
                    float2 r = *(const float2*)(g_p0buf + (size_t)m * Nd + n);
                    float2 o = make_float2(v0 + r.x, v1 + r.y);
                    *(float2*)(g_pbuf + (size_t)m * Nd + n) = o;
                }
            }
        }
    }
}

// ---------------- K4a: partial q = Wq^T p_last ----------------
__global__ void qk_q_kernel(const float* __restrict__ Wq) {
    int l = blockIdx.x, c = blockIdx.y;
    int j = threadIdx.x;
    __shared__ float pl[32];
    if (j < 32) pl[j] = g_pbuf[(size_t)(Sq - 1) * Dq + c * 32 + j];
    __syncthreads();
    const float* wq = Wq + (size_t)l * Dq * Dq + (size_t)c * 32 * Dq;
    float acc = 0.f;
#pragma unroll
    for (int i = 0; i < 32; i++) acc += pl[i] * wq[(size_t)i * Dq + j];
    g_qpart[(l * 8 + c) * Dq + j] = acc;
}

// ---------------- K4b: m_l = Wk_l @ q_l ----------------
__global__ void qk_m_kernel(const float* __restrict__ Wk) {
    int l = blockIdx.x;
    int tid = threadIdx.x;
    int warp = tid >> 5, lane = tid & 31;
    __shared__ float qs[Dq];
    {
        float acc = 0.f;
#pragma unroll
        for (int c = 0; c < 8; c++) acc += g_qpart[(l * 8 + c) * Dq + tid];
        qs[tid] = acc;
    }
    __syncthreads();
    int j = blockIdx.y * 8 + warp;
    const float* wk = Wk + (size_t)l * Dq * Dq + (size_t)j * Dq;
    float m = 0.f;
#pragma unroll
    for (int i = 0; i < 8; i++) {
        int idx = lane + i * 32;
        m += wk[idx] * qs[idx];
    }
#pragma unroll
    for (int o = 16; o; o >>= 1) m += __shfl_xor_sync(0xffffffffu, m, o);
    if (lane == 0) g_mbuf[l * Dq + j] = m;
}

// ---------------- K5: scores ----------------
__global__ void score_kernel() {
    int l = blockIdx.y;
    int warp = threadIdx.x >> 5, lane = threadIdx.x & 31;
    int t = blockIdx.x * 8 + warp;
    const float* p = g_pbuf + (size_t)t * Dq;
    const float* m = g_mbuf + l * Dq;
    float acc = 0.f;
#pragma unroll
    for (int i = 0; i < 8; i++) {
        int d = lane + i * 32;
        acc += p[d] * m[d];
    }
#pragma unroll
    for (int o = 16; o; o >>= 1) acc += __shfl_xor_sync(0xffffffffu, acc, o);
    if (lane == 0) g_sbuf[l * Sq + t] = acc * 0.0625f;
}

// ---------------- K6: softmax ----------------
__global__ void softmax_kernel() {
    int l = blockIdx.x;
    int tid = threadIdx.x;
    __shared__ float red[32];
    __shared__ float bc;
    float v[4];
    float mx = -1e30f;
#pragma unroll
    for (int i = 0; i < 4; i++) {
        v[i] = g_sbuf[l * Sq + tid + i * 1024];
        mx = fmaxf(mx, v[i]);
    }
#pragma unroll
    for (int o = 16; o; o >>= 1) mx = fmaxf(mx, __shfl_xor_sync(0xffffffffu, mx, o));
    if ((tid & 31) == 0) red[tid >> 5] = mx;
    __syncthreads();
    if (tid < 32) {
        float m = red[tid];
#pragma unroll
        for (int o = 16; o; o >>= 1) m = fmaxf(m, __shfl_xor_sync(0xffffffffu, m, o));
        if (tid == 0) bc = m;
    }
    __syncthreads();
    float M = bc;
    float sum = 0.f;
#pragma unroll
    for (int i = 0; i < 4; i++) {
        v[i] = expf(v[i] - M);
        sum += v[i];
    }
#pragma unroll
    for (int o = 16; o; o >>= 1) sum += __shfl_xor_sync(0xffffffffu, sum, o);
    __syncthreads();
    if ((tid & 31) == 0) red[tid >> 5] = sum;
    __syncthreads();
    if (tid < 32) {
        float s2 = red[tid];
#pragma unroll
        for (int o = 16; o; o >>= 1) s2 += __shfl_xor_sync(0xffffffffu, s2, o);
        if (tid == 0) bc = s2;
    }
    __syncthreads();
    float inv = 1.0f / bc;
#pragma unroll
    for (int i = 0; i < 4; i++) g_abuf[l * Sq + tid + i * 1024] = v[i] * inv;
}

// ---------------- K7: ctx partials ----------------
__global__ void ctx_kernel() {
    int chunk = blockIdx.x;
    int b = blockIdx.y;
    int d = threadIdx.x;
    __shared__ float as_[Lq][128];
    for (int i = d; i < Lq * 128; i += 256) {
        int l = i >> 7, t = i & 127;
        as_[l][t] = g_abuf[l * Sq + chunk * 128 + t];
    }
    __syncthreads();
    float acc[Lq] = {};
    const float* ep = g_ebuf + ((size_t)b * Sq + (size_t)chunk * 128) * Dq + d;
#pragma unroll 4
    for (int t = 0; t < 128; t++) {
        float ev = ep[(size_t)t * Dq];
#pragma unroll
        for (int l = 0; l < Lq; l++) acc[l] += as_[l][t] * ev;
    }
#pragma unroll
    for (int l = 0; l < Lq; l++)
        g_ctxpart[(((size_t)chunk * Lq + l) * Bq + b) * Dq + d] = acc[l];
}

// ---------------- K8: ctx reduce ----------------
__global__ void ctx_reduce_kernel() {
    int l = blockIdx.x, b = blockIdx.y, d = threadIdx.x;
    float acc = 0.f;
#pragma unroll
    for (int c = 0; c < 32; c++)
        acc += g_ctxpart[(((size_t)c * Lq + l) * Bq + b) * Dq + d];
    g_ctx[((size_t)l * Bq + b) * Dq + d] = acc;
}

// ---------------- K9: Wv projection ----------------
__global__ void vproj_kernel(const float* __restrict__ Wv) {
    int l = blockIdx.x, b = blockIdx.y, d = threadIdx.x;
    __shared__ float c[Dq];
    c[d] = g_ctx[((size_t)l * Bq + b) * Dq + d];
    __syncthreads();
    const float* wv = Wv + (size_t)l * Dq * Dq;
    float acc = 0.f;
#pragma unroll 4
    for (int k = 0; k < Dq; k++) acc += c[k] * wv[(size_t)k * Dq + d];
    g_attnout[((size_t)l * Bq + b) * Dq + d] = acc;
}

// ---------------- K10: final LN ----------------
__global__ void final_ln_kernel(const float* __restrict__ g_out_w) {
    int b = blockIdx.x, d = threadIdx.x;
    float x = g_ebuf[((size_t)b * Sq + Sq - 1) * Dq + d] + g_p0buf[(size_t)(Sq - 1) * Dq + d];
#pragma unroll
    for (int l = 0; l < Lq; l++) x += g_attnout[((size_t)l * Bq + b) * Dq + d];
    float2 r = blockReduceSum2_256(x, x * x);
    float mean = r.x * (1.0f / Dq);
    float var = r.y * (1.0f / Dq) - mean * mean;
    g_xhat[b * Dq + d] = (x - mean) * rsqrtf(var + 1e-5f) * g_out_w[d];
}

// ---------------- K11: logits ----------------
__global__ void logits_kernel(const float* __restrict__ wte,
                              const float* __restrict__ gew,
                              float* __restrict__ out) {
    __shared__ float xs[Bq * Dq];
    __shared__ float gs[Dq];
    int tid = threadIdx.x;
    for (int i = tid; i < Bq * Dq; i += 256) xs[i] = g_xhat[i];
    gs[tid] = gew[tid];
    __syncthreads();
    int warp = tid >> 5, lane = tid & 31;
    int v = blockIdx.x * 8 + warp;
    const float* w = wte + (size_t)v * Dq;
    float wv[8];
    float s = 0.f, ss = 0.f;
#pragma unroll
    for (int i = 0; i < 8; i++) {
        wv[i] = w[lane + i * 32];
        s += wv[i];
        ss += wv[i] * wv[i];
    }
#pragma unroll
    for (int o = 16; o; o >>= 1) {
        s += __shfl_xor_sync(0xffffffffu, s, o);
        ss += __shfl_xor_sync(0xffffffffu, ss, o);
    }
    float mean = s * (1.0f / Dq);
    float var = ss * (1.0f / Dq) - mean * mean;
    float rstd = rsqrtf(var + 1e-5f);
    float wn[8];
#pragma unroll
    for (int i = 0; i < 8; i++) wn[i] = (wv[i] - mean) * rstd * gs[lane + i * 32];
#pragma unroll
    for (int b = 0; b < Bq; b++) {
        float dot = 0.f;
#pragma unroll
        for (int i = 0; i < 8; i++) dot += wn[i] * xs[b * Dq + lane + i * 32];
#pragma unroll
        for (int o = 16; o; o >>= 1) dot += __shfl_xor_sync(0xffffffffu, dot, o);
        if (lane == 0) out[(size_t)b * Vq + v] = dot;
    }
}

// ---------------- launch ----------------
extern "C" void kernel_launch(void* const* d_in, const int* in_sizes, int n_in,
                              void* d_out, int out_size) {
    const int* tokens = (const int*)d_in[0];
    const float* wte = (const float*)d_in[1];
    const float* wpe = (const float*)d_in[2];
    const float* g_e = (const float*)d_in[3];
    const float* g_p = (const float*)d_in[4];
    const float* g_out = (const float*)d_in[5];
    const float* ff_w1 = (const float*)d_in[6];
    const float* ff_w2 = (const float*)d_in[7];
    const float* Wq = (const float*)d_in[8];
    const float* Wk = (const float*)d_in[9];
    const float* Wv = (const float*)d_in[10];
    float* out = (float*)d_out;

    __nv_bfloat16* pA;   cudaGetSymbolAddress((void**)&pA, g_pA);
    __nv_bfloat16* w1t;  cudaGetSymbolAddress((void**)&w1t, g_w1t);
    __nv_bfloat16* w2t;  cudaGetSymbolAddress((void**)&w2t, g_w2t);
    float* p0;           cudaGetSymbolAddress((void**)&p0, g_p0buf);

    // weight transposes (independent of activations)
    transpose_bf16_kernel<<<dim3(Hq / 32, Dq / 32), dim3(32, 8)>>>(ff_w1, w1t, Dq, Hq);
    transpose_bf16_kernel<<<dim3(Dq / 32, Hq / 32), dim3(32, 8)>>>(ff_w2, w2t, Hq, Dq);
    // 1. embeddings + positional LN
    embed_ln_kernel<<<Bq * Sq + Sq, 256>>>(tokens, wte, wpe, g_e, g_p);
    // bf16 copy of p_raw
    conv_bf16_kernel<<<(Sq * Dq / 4) / 256, 256>>>(p0, pA);
    // 2/3. FFN on tensor cores (mma.sync bf16)
    ffn_mma_kernel<0><<<dim3(Hq / 64, Sq / 128), 256>>>();
    ffn_mma_kernel<1><<<dim3(Dq / 64, Sq / 128), 256>>>();
    // 4. per-layer score direction m_l
    qk_q_kernel<<<dim3(Lq, 8), 256>>>(Wq);
    qk_m_kernel<<<dim3(Lq, 32), 256>>>(Wk);
    // 5. scores
    score_kernel<<<dim3(Sq / 8, Lq), 256>>>();
    // 6. softmax
    softmax_kernel<<<Lq, 1024>>>();
    // 7/8. ctx
    ctx_kernel<<<dim3(32, Bq), 256>>>();
    ctx_reduce_kernel<<<dim3(Lq, Bq), 256>>>();
    // 9. Wv projection
    vproj_kernel<<<dim3(Lq, Bq), 256>>>(Wv);
    // 10. final LN
    final_ln_kernel<<<Bq, 256>>>(g_out);
    // 11. logits
    logits_kernel<<<Vq / 8, 256>>>(wte, g_e, out);
}

// round 5
// speedup vs baseline: 2.6397x; 1.1943x over previous
#include <cuda_runtime.h>
#include <cuda_bf16.h>
#include <math.h>
#include <stdint.h>

#define Bq 4
#define Sq 4096
#define Dq 256
#define Lq 6
#define Vq 32000
#define Hq 1024

// ---------------- scratch (no allocations allowed) ----------------
__device__ float g_ebuf[(size_t)Bq * Sq * Dq];   // e = ln(wte[tokens])        16MB
__device__ float g_p0buf[Sq * Dq];               // p_raw = ln(wpe[:S])         4MB
__device__ float g_pbuf[Sq * Dq];                // p (post-FFN, fp32)          4MB
__device__ __nv_bfloat16 g_pA[Sq * Dq];          // bf16(p_raw)                 2MB
__device__ __nv_bfloat16 g_hbf[(size_t)Sq * Hq]; // bf16 FFN hidden             8MB
__device__ __nv_bfloat16 g_w1t[Hq * Dq];         // ff_w1^T  [H][D] bf16
__device__ __nv_bfloat16 g_w2t[Dq * Hq];         // ff_w2^T  [D][H] bf16
__device__ float g_qpart[Lq * 8 * Dq];
__device__ float g_mbuf[Lq * Dq];
__device__ float g_sbuf[Lq * Sq];
__device__ float g_abuf[Lq * Sq];
__device__ float g_ctxpart[32 * Lq * Bq * Dq];
__device__ float g_ctx[Lq * Bq * Dq];
__device__ float g_attnout[Lq * Bq * Dq];
__device__ float g_xhat[Bq * Dq];

// ---------------- helpers ----------------
__device__ __forceinline__ uint32_t smem_u32(const void* p) {
    uint32_t a;
    asm("{ .reg .u64 t; cvta.to.shared.u64 t, %1; cvt.u32.u64 %0, t; }" : "=r"(a) : "l"(p));
    return a;
}

__device__ __forceinline__ void ldsm_x4(uint32_t* r, uint32_t addr) {
    asm volatile("ldmatrix.sync.aligned.m8n8.x4.shared.b16 {%0,%1,%2,%3}, [%4];"
                 : "=r"(r[0]), "=r"(r[1]), "=r"(r[2]), "=r"(r[3]) : "r"(addr));
}

__device__ __forceinline__ void mma_bf16(float* c, const uint32_t* a, const uint32_t* b) {
    asm volatile(
        "mma.sync.aligned.m16n8k16.row.col.f32.bf16.bf16.f32 "
        "{%0,%1,%2,%3}, {%4,%5,%6,%7}, {%8,%9}, {%0,%1,%2,%3};"
        : "+f"(c[0]), "+f"(c[1]), "+f"(c[2]), "+f"(c[3])
        : "r"(a[0]), "r"(a[1]), "r"(a[2]), "r"(a[3]), "r"(b[0]), "r"(b[1]));
}

__device__ __forceinline__ void cp_async16(uint32_t saddr, const void* gptr) {
    asm volatile("cp.async.cg.shared.global [%0], [%1], 16;" :: "r"(saddr), "l"(gptr));
}
#define CP_COMMIT() asm volatile("cp.async.commit_group;")
template <int N>
__device__ __forceinline__ void cp_wait() {
    asm volatile("cp.async.wait_group %0;" :: "n"(N));
}

__device__ __forceinline__ float2 blockReduceSum2_256(float a, float b) {
    __shared__ float sa[8], sb[8];
    int lane = threadIdx.x & 31, w = threadIdx.x >> 5;
#pragma unroll
    for (int o = 16; o; o >>= 1) {
        a += __shfl_xor_sync(0xffffffffu, a, o);
        b += __shfl_xor_sync(0xffffffffu, b, o);
    }
    if (lane == 0) { sa[w] = a; sb[w] = b; }
    __syncthreads();
    if (w == 0) {
        a = (lane < 8) ? sa[lane] : 0.f;
        b = (lane < 8) ? sb[lane] : 0.f;
#pragma unroll
        for (int o = 4; o; o >>= 1) {
            a += __shfl_xor_sync(0xffffffffu, a, o);
            b += __shfl_xor_sync(0xffffffffu, b, o);
        }
        if (lane == 0) { sa[0] = a; sb[0] = b; }
    }
    __syncthreads();
    float ra = sa[0], rb = sb[0];
    __syncthreads();
    return make_float2(ra, rb);
}

// ---------------- K1: embedding + positional LN (warp per row) ----------
// Also writes bf16(p_raw) for the FFN A operand (conv fused).
__global__ void __launch_bounds__(256) embed_ln_kernel(
    const int* __restrict__ tokens, const float* __restrict__ wte,
    const float* __restrict__ wpe, const float* __restrict__ gew,
    const float* __restrict__ gpw) {
    int warp = threadIdx.x >> 5, lane = threadIdx.x & 31;
    int row = blockIdx.x * 8 + warp;
    const float* src;
    float* dst;
    const float* g;
    __nv_bfloat16* dst16 = nullptr;
    if (row < Bq * Sq) {
        int tok = __ldg(tokens + row);
        src = wte + (size_t)tok * Dq;
        dst = g_ebuf + (size_t)row * Dq;
        g = gew;
    } else {
        int s = row - Bq * Sq;
        src = wpe + (size_t)s * Dq;
        dst = g_p0buf + (size_t)s * Dq;
        dst16 = g_pA + (size_t)s * Dq;
        g = gpw;
    }
    float4 v0 = *(const float4*)(src + lane * 8);
    float4 v1 = *(const float4*)(src + lane * 8 + 4);
    float s1 = v0.x + v0.y + v0.z + v0.w + v1.x + v1.y + v1.z + v1.w;
    float s2 = v0.x * v0.x + v0.y * v0.y + v0.z * v0.z + v0.w * v0.w +
               v1.x * v1.x + v1.y * v1.y + v1.z * v1.z + v1.w * v1.w;
#pragma unroll
    for (int o = 16; o; o >>= 1) {
        s1 += __shfl_xor_sync(0xffffffffu, s1, o);
        s2 += __shfl_xor_sync(0xffffffffu, s2, o);
    }
    float mean = s1 * (1.0f / Dq);
    float var = s2 * (1.0f / Dq) - mean * mean;
    float rstd = rsqrtf(var + 1e-5f);
    float4 g0 = *(const float4*)(g + lane * 8);
    float4 g1 = *(const float4*)(g + lane * 8 + 4);
    float4 o0, o1;
    o0.x = (v0.x - mean) * rstd * g0.x;
    o0.y = (v0.y - mean) * rstd * g0.y;
    o0.z = (v0.z - mean) * rstd * g0.z;
    o0.w = (v0.w - mean) * rstd * g0.w;
    o1.x = (v1.x - mean) * rstd * g1.x;
    o1.y = (v1.y - mean) * rstd * g1.y;
    o1.z = (v1.z - mean) * rstd * g1.z;
    o1.w = (v1.w - mean) * rstd * g1.w;
    *(float4*)(dst + lane * 8) = o0;
    *(float4*)(dst + lane * 8 + 4) = o1;
    if (dst16) {
        __nv_bfloat162 b0 = __floats2bfloat162_rn(o0.x, o0.y);
        __nv_bfloat162 b1 = __floats2bfloat162_rn(o0.z, o0.w);
        __nv_bfloat162 b2 = __floats2bfloat162_rn(o1.x, o1.y);
        __nv_bfloat162 b3 = __floats2bfloat162_rn(o1.z, o1.w);
        uint4 u;
        u.x = reinterpret_cast<uint32_t&>(b0);
        u.y = reinterpret_cast<uint32_t&>(b1);
        u.z = reinterpret_cast<uint32_t&>(b2);
        u.w = reinterpret_cast<uint32_t&>(b3);
        *(uint4*)(dst16 + lane * 8) = u;
    }
}

// ---------------- prep: transpose fp32 [R][C] -> bf16 [C][R] ----------------
__global__ void transpose_bf16_kernel(const float* __restrict__ src,
                                      __nv_bfloat16* __restrict__ dst, int R, int C) {
    __shared__ float t[32][33];
    int c0 = blockIdx.x * 32, r0 = blockIdx.y * 32;
    int x = threadIdx.x, y = threadIdx.y;  // 32 x 8
#pragma unroll
    for (int i = 0; i < 32; i += 8) t[y + i][x] = src[(size_t)(r0 + y + i) * C + c0 + x];
    __syncthreads();
#pragma unroll
    for (int i = 0; i < 32; i += 8)
        dst[(size_t)(c0 + y + i) * R + r0 + x] = __float2bfloat16(t[x][y + i]);
}

// ---------------- FFN GEMMs via mma.sync + cp.async 2-stage pipeline ------
// MODE 0: h = gelu(p_raw @ ff_w1), K=256,  N=1024, out bf16 g_hbf
// MODE 1: p = p_raw + h @ ff_w2,   K=1024, N=256,  out fp32 g_pbuf
// CTA tile 128x64, BK=64; 8 warps (4 m x 2 n), warp tile 32x32.
template <int MODE>
__global__ void __launch_bounds__(256) ffn_mma_kernel() {
    constexpr int Kd = (MODE == 0) ? Dq : Hq;
    constexpr int Nd = (MODE == 0) ? Hq : Dq;
    constexpr int BK = 64, LDS = 72;  // 144B row stride (16B aligned)
    constexpr int NCH = Kd / BK;
    const __nv_bfloat16* __restrict__ A = (MODE == 0) ? g_pA : g_hbf;
    const __nv_bfloat16* __restrict__ Bt = (MODE == 0) ? g_w1t : g_w2t;

    extern __shared__ __nv_bfloat16 dynsm[];
    __nv_bfloat16* AsBase = dynsm;                    // 2 stages x 128 x LDS
    __nv_bfloat16* BsBase = dynsm + 2 * 128 * LDS;    // 2 stages x 64 x LDS

    int tid = threadIdx.x, wid = tid >> 5, lane = tid & 31;
    int warp_m = wid & 3, warp_n = wid >> 2;
    int m0 = blockIdx.y * 128, n0 = blockIdx.x * 64;

    int a_row = warp_m * 32 + ((lane >> 3) & 1) * 8 + (lane & 7);
    int a_col = (lane >> 4) * 8;
    int b_row = warp_n * 32 + ((lane >> 4) & 1) * 8 + (lane & 7);
    int b_col = ((lane >> 3) & 1) * 8;

    int lr = tid >> 3, lc = (tid & 7) * 8;  // load coords: 32 rows x 8 chunks per pass

    auto load_stage = [&](int st, int k0) {
        __nv_bfloat16* As = AsBase + st * 128 * LDS;
        __nv_bfloat16* Bs = BsBase + st * 64 * LDS;
#pragma unroll
        for (int i = 0; i < 4; i++) {
            int r = lr + i * 32;
            cp_async16(smem_u32(As + r * LDS + lc), A + (size_t)(m0 + r) * Kd + k0 + lc);
        }
#pragma unroll
        for (int i = 0; i < 2; i++) {
            int r = lr + i * 32;
            cp_async16(smem_u32(Bs + r * LDS + lc), Bt + (size_t)(n0 + r) * Kd + k0 + lc);
        }
        CP_COMMIT();
    };

    float c[2][4][4] = {};

    load_stage(0, 0);
    for (int ch = 0; ch < NCH; ch++) {
        if (ch + 1 < NCH) {
            load_stage((ch + 1) & 1, (ch + 1) * BK);
            cp_wait<1>();
        } else {
            cp_wait<0>();
        }
        __syncthreads();
        int st = ch & 1;
        uint32_t As_base = smem_u32(AsBase + st * 128 * LDS);
        uint32_t Bs_base = smem_u32(BsBase + st * 64 * LDS);
#pragma unroll
        for (int kk = 0; kk < BK / 16; kk++) {
            uint32_t a[2][4], b[2][4];
#pragma unroll
            for (int mt = 0; mt < 2; mt++) {
                uint32_t addr = As_base + ((a_row + mt * 16) * LDS + kk * 16 + a_col) * 2;
                ldsm_x4(a[mt], addr);
            }
#pragma unroll
            for (int nt2 = 0; nt2 < 2; nt2++) {
                uint32_t addr = Bs_base + ((b_row + nt2 * 16) * LDS + kk * 16 + b_col) * 2;
                ldsm_x4(b[nt2], addr);
            }
#pragma unroll
            for (int mt = 0; mt < 2; mt++)
#pragma unroll
                for (int nt2 = 0; nt2 < 2; nt2++) {
                    mma_bf16(c[mt][nt2 * 2 + 0], a[mt], &b[nt2][0]);
                    mma_bf16(c[mt][nt2 * 2 + 1], a[mt], &b[nt2][2]);
                }
        }
        __syncthreads();
    }

    // epilogue
    int group = lane >> 2, tg = lane & 3;
#pragma unroll
    for (int mt = 0; mt < 2; mt++) {
#pragma unroll
        for (int nt = 0; nt < 4; nt++) {
#pragma unroll
            for (int half = 0; half < 2; half++) {
                int m = m0 + warp_m * 32 + mt * 16 + group + half * 8;
                int n = n0 + warp_n * 32 + nt * 8 + tg * 2;
                float v0 = c[mt][nt][half * 2 + 0];
                float v1 = c[mt][nt][half * 2 + 1];
                if (MODE == 0) {
                    v0 = 0.5f * v0 * (1.0f + erff(v0 * 0.70710678118654752f));
                    v1 = 0.5f * v1 * (1.0f + erff(v1 * 0.70710678118654752f));
                    __nv_bfloat162 h = __floats2bfloat162_rn(v0, v1);
                    *(uint32_t*)&g_hbf[(size_t)m * Nd + n] = reinterpret_cast<uint32_t&>(h);
                } else {
                    float2 r = *(const float2*)(g_p0buf + (size_t)m * Nd + n);
                    float2 o = make_float2(v0 + r.x, v1 + r.y);
                    *(float2*)(g_pbuf + (size_t)m * Nd + n) = o;
                }
            }
        }
    }
}

// ---------------- K4a: partial q = Wq^T p_last ----------------
__global__ void qk_q_kernel(const float* __restrict__ Wq) {
    int l = blockIdx.x, c = blockIdx.y;
    int j = threadIdx.x;
    __shared__ float pl[32];
    if (j < 32) pl[j] = g_pbuf[(size_t)(Sq - 1) * Dq + c * 32 + j];
    __syncthreads();
    const float* wq = Wq + (size_t)l * Dq * Dq + (size_t)c * 32 * Dq;
    float acc = 0.f;
#pragma unroll
    for (int i = 0; i < 32; i++) acc += pl[i] * wq[(size_t)i * Dq + j];
    g_qpart[(l * 8 + c) * Dq + j] = acc;
}

// ---------------- K4b: m_l = Wk_l @ q_l ----------------
__global__ void qk_m_kernel(const float* __restrict__ Wk) {
    int l = blockIdx.x;
    int tid = threadIdx.x;
    int warp = tid >> 5, lane = tid & 31;
    __shared__ float qs[Dq];
    {
        float acc = 0.f;
#pragma unroll
        for (int c = 0; c < 8; c++) acc += g_qpart[(l * 8 + c) * Dq + tid];
        qs[tid] = acc;
    }
    __syncthreads();
    int j = blockIdx.y * 8 + warp;
    const float* wk = Wk + (size_t)l * Dq * Dq + (size_t)j * Dq;
    float m = 0.f;
#pragma unroll
    for (int i = 0; i < 8; i++) {
        int idx = lane + i * 32;
        m += wk[idx] * qs[idx];
    }
#pragma unroll
    for (int o = 16; o; o >>= 1) m += __shfl_xor_sync(0xffffffffu, m, o);
    if (lane == 0) g_mbuf[l * Dq + j] = m;
}

// ---------------- K5: scores ----------------
__global__ void score_kernel() {
    int l = blockIdx.y;
    int warp = threadIdx.x >> 5, lane = threadIdx.x & 31;
    int t = blockIdx.x * 8 + warp;
    const float* p = g_pbuf + (size_t)t * Dq;
    const float* m = g_mbuf + l * Dq;
    float acc = 0.f;
#pragma unroll
    for (int i = 0; i < 8; i++) {
        int d = lane + i * 32;
        acc += p[d] * m[d];
    }
#pragma unroll
    for (int o = 16; o; o >>= 1) acc += __shfl_xor_sync(0xffffffffu, acc, o);
    if (lane == 0) g_sbuf[l * Sq + t] = acc * 0.0625f;
}

// ---------------- K6: softmax ----------------
__global__ void softmax_kernel() {
    int l = blockIdx.x;
    int tid = threadIdx.x;
    __shared__ float red[32];
    __shared__ float bc;
    float v[4];
    float mx = -1e30f;
#pragma unroll
    for (int i = 0; i < 4; i++) {
        v[i] = g_sbuf[l * Sq + tid + i * 1024];
        mx = fmaxf(mx, v[i]);
    }
#pragma unroll
    for (int o = 16; o; o >>= 1) mx = fmaxf(mx, __shfl_xor_sync(0xffffffffu, mx, o));
    if ((tid & 31) == 0) red[tid >> 5] = mx;
    __syncthreads();
    if (tid < 32) {
        float m = red[tid];
#pragma unroll
        for (int o = 16; o; o >>= 1) m = fmaxf(m, __shfl_xor_sync(0xffffffffu, m, o));
        if (tid == 0) bc = m;
    }
    __syncthreads();
    float M = bc;
    float sum = 0.f;
#pragma unroll
    for (int i = 0; i < 4; i++) {
        v[i] = expf(v[i] - M);
        sum += v[i];
    }
#pragma unroll
    for (int o = 16; o; o >>= 1) sum += __shfl_xor_sync(0xffffffffu, sum, o);
    __syncthreads();
    if ((tid & 31) == 0) red[tid >> 5] = sum;
    __syncthreads();
    if (tid < 32) {
        float s2 = red[tid];
#pragma unroll
        for (int o = 16; o; o >>= 1) s2 += __shfl_xor_sync(0xffffffffu, s2, o);
        if (tid == 0) bc = s2;
    }
    __syncthreads();
    float inv = 1.0f / bc;
#pragma unroll
    for (int i = 0; i < 4; i++) g_abuf[l * Sq + tid + i * 1024] = v[i] * inv;
}

// ---------------- K7: ctx partials ----------------
__global__ void ctx_kernel() {
    int chunk = blockIdx.x;
    int b = blockIdx.y;
    int d = threadIdx.x;
    __shared__ float as_[Lq][128];
    for (int i = d; i < Lq * 128; i += 256) {
        int l = i >> 7, t = i & 127;
        as_[l][t] = g_abuf[l * Sq + chunk * 128 + t];
    }
    __syncthreads();
    float acc[Lq] = {};
    const float* ep = g_ebuf + ((size_t)b * Sq + (size_t)chunk * 128) * Dq + d;
#pragma unroll 4
    for (int t = 0; t < 128; t++) {
        float ev = ep[(size_t)t * Dq];
#pragma unroll
        for (int l = 0; l < Lq; l++) acc[l] += as_[l][t] * ev;
    }
#pragma unroll
    for (int l = 0; l < Lq; l++)
        g_ctxpart[(((size_t)chunk * Lq + l) * Bq + b) * Dq + d] = acc[l];
}

// ---------------- K8: ctx reduce ----------------
__global__ void ctx_reduce_kernel() {
    int l = blockIdx.x, b = blockIdx.y, d = threadIdx.x;
    float acc = 0.f;
#pragma unroll
    for (int c = 0; c < 32; c++)
        acc += g_ctxpart[(((size_t)c * Lq + l) * Bq + b) * Dq + d];
    g_ctx[((size_t)l * Bq + b) * Dq + d] = acc;
}

// ---------------- K9: Wv projection ----------------
__global__ void vproj_kernel(const float* __restrict__ Wv) {
    int l = blockIdx.x, b = blockIdx.y, d = threadIdx.x;
    __shared__ float c[Dq];
    c[d] = g_ctx[((size_t)l * Bq + b) * Dq + d];
    __syncthreads();
    const float* wv = Wv + (size_t)l * Dq * Dq;
    float acc = 0.f;
#pragma unroll 4
    for (int k = 0; k < Dq; k++) acc += c[k] * wv[(size_t)k * Dq + d];
    g_attnout[((size_t)l * Bq + b) * Dq + d] = acc;
}

// ---------------- K10: final LN ----------------
__global__ void final_ln_kernel(const float* __restrict__ g_out_w) {
    int b = blockIdx.x, d = threadIdx.x;
    float x = g_ebuf[((size_t)b * Sq + Sq - 1) * Dq + d] + g_p0buf[(size_t)(Sq - 1) * Dq + d];
#pragma unroll
    for (int l = 0; l < Lq; l++) x += g_attnout[((size_t)l * Bq + b) * Dq + d];
    float2 r = blockReduceSum2_256(x, x * x);
    float mean = r.x * (1.0f / Dq);
    float var = r.y * (1.0f / Dq) - mean * mean;
    g_xhat[b * Dq + d] = (x - mean) * rsqrtf(var + 1e-5f) * g_out_w[d];
}

// ---------------- K11: logits ----------------
__global__ void logits_kernel(const float* __restrict__ wte,
                              const float* __restrict__ gew,
                              float* __restrict__ out) {
    __shared__ float xs[Bq * Dq];
    __shared__ float gs[Dq];
    int tid = threadIdx.x;
    for (int i = tid; i < Bq * Dq; i += 256) xs[i] = g_xhat[i];
    gs[tid] = gew[tid];
    __syncthreads();
    int warp = tid >> 5, lane = tid & 31;
    int v = blockIdx.x * 8 + warp;
    const float* w = wte + (size_t)v * Dq;
    float wv[8];
    float s = 0.f, ss = 0.f;
#pragma unroll
    for (int i = 0; i < 8; i++) {
        wv[i] = w[lane + i * 32];
        s += wv[i];
        ss += wv[i] * wv[i];
    }
#pragma unroll
    for (int o = 16; o; o >>= 1) {
        s += __shfl_xor_sync(0xffffffffu, s, o);
        ss += __shfl_xor_sync(0xffffffffu, ss, o);
    }
    float mean = s * (1.0f / Dq);
    float var = ss * (1.0f / Dq) - mean * mean;
    float rstd = rsqrtf(var + 1e-5f);
    float wn[8];
#pragma unroll
    for (int i = 0; i < 8; i++) wn[i] = (wv[i] - mean) * rstd * gs[lane + i * 32];
#pragma unroll
    for (int b = 0; b < Bq; b++) {
        float dot = 0.f;
#pragma unroll
        for (int i = 0; i < 8; i++) dot += wn[i] * xs[b * Dq + lane + i * 32];
#pragma unroll
        for (int o = 16; o; o >>= 1) dot += __shfl_xor_sync(0xffffffffu, dot, o);
        if (lane == 0) out[(size_t)b * Vq + v] = dot;
    }
}

// ---------------- launch ----------------
extern "C" void kernel_launch(void* const* d_in, const int* in_sizes, int n_in,
                              void* d_out, int out_size) {
    const int* tokens = (const int*)d_in[0];
    const float* wte = (const float*)d_in[1];
    const float* wpe = (const float*)d_in[2];
    const float* g_e = (const float*)d_in[3];
    const float* g_p = (const float*)d_in[4];
    const float* g_out = (const float*)d_in[5];
    const float* ff_w1 = (const float*)d_in[6];
    const float* ff_w2 = (const float*)d_in[7];
    const float* Wq = (const float*)d_in[8];
    const float* Wk = (const float*)d_in[9];
    const float* Wv = (const float*)d_in[10];
    float* out = (float*)d_out;

    __nv_bfloat16* w1t;  cudaGetSymbolAddress((void**)&w1t, g_w1t);
    __nv_bfloat16* w2t;  cudaGetSymbolAddress((void**)&w2t, g_w2t);

    constexpr int FFN_SMEM = 2 * (128 + 64) * 72 * 2;  // 55296 bytes
    cudaFuncSetAttribute(ffn_mma_kernel<0>, cudaFuncAttributeMaxDynamicSharedMemorySize, FFN_SMEM);
    cudaFuncSetAttribute(ffn_mma_kernel<1>, cudaFuncAttributeMaxDynamicSharedMemorySize, FFN_SMEM);

    // weight transposes (independent of activations)
    transpose_bf16_kernel<<<dim3(Hq / 32, Dq / 32), dim3(32, 8)>>>(ff_w1, w1t, Dq, Hq);
    transpose_bf16_kernel<<<dim3(Dq / 32, Hq / 32), dim3(32, 8)>>>(ff_w2, w2t, Hq, Dq);
    // 1. embeddings + positional LN (+ fused bf16 p_raw)
    embed_ln_kernel<<<(Bq * Sq + Sq) / 8, 256>>>(tokens, wte, wpe, g_e, g_p);
    // 2/3. FFN on tensor cores (pipelined)
    ffn_mma_kernel<0><<<dim3(Hq / 64, Sq / 128), 256, FFN_SMEM>>>();
    ffn_mma_kernel<1><<<dim3(Dq / 64, Sq / 128), 256, FFN_SMEM>>>();
    // 4. per-layer score direction m_l
    qk_q_kernel<<<dim3(Lq, 8), 256>>>(Wq);
    qk_m_kernel<<<dim3(Lq, 32), 256>>>(Wk);
    // 5. scores
    score_kernel<<<dim3(Sq / 8, Lq), 256>>>();
    // 6. softmax
    softmax_kernel<<<Lq, 1024>>>();
    // 7/8. ctx
    ctx_kernel<<<dim3(32, Bq), 256>>>();
    ctx_reduce_kernel<<<dim3(Lq, Bq), 256>>>();
    // 9. Wv projection
    vproj_kernel<<<dim3(Lq, Bq), 256>>>(Wv);
    // 10. final LN
    final_ln_kernel<<<Bq, 256>>>(g_out);
    // 11. logits
    logits_kernel<<<Vq / 8, 256>>>(wte, g_e, out);
}

// round 6
// speedup vs baseline: 2.6711x; 1.0119x over previous
#include <cuda_runtime.h>
#include <cuda_bf16.h>
#include <math.h>
#include <stdint.h>

#define Bq 4
#define Sq 4096
#define Dq 256
#define Lq 6
#define Vq 32000
#define Hq 1024

// ---------------- scratch (no allocations allowed) ----------------
__device__ float g_ebuf[(size_t)Bq * Sq * Dq];   // e = ln(wte[tokens])        16MB
__device__ float g_p0buf[Sq * Dq];               // p_raw = ln(wpe[:S])         4MB
__device__ float g_pbuf[Sq * Dq];                // p (post-FFN, fp32)          4MB
__device__ __nv_bfloat16 g_pA[Sq * Dq];          // bf16(p_raw)                 2MB
__device__ __nv_bfloat16 g_hbf[(size_t)Sq * Hq]; // bf16 FFN hidden             8MB
__device__ __nv_bfloat16 g_w1t[Hq * Dq];         // ff_w1^T  [H][D] bf16
__device__ __nv_bfloat16 g_w2t[Dq * Hq];         // ff_w2^T  [D][H] bf16
__device__ float g_qpart[Lq * 8 * Dq];
__device__ float g_mbuf[Lq * Dq];
__device__ float g_sbuf[Lq * Sq];
__device__ float g_abuf[Lq * Sq];
__device__ float g_ctxpart[32 * Lq * Bq * Dq];
__device__ float g_attnout[Lq * Bq * Dq];
__device__ float g_xhat[Bq * Dq];

// ---------------- helpers ----------------
__device__ __forceinline__ uint32_t smem_u32(const void* p) {
    uint32_t a;
    asm("{ .reg .u64 t; cvta.to.shared.u64 t, %1; cvt.u32.u64 %0, t; }" : "=r"(a) : "l"(p));
    return a;
}

__device__ __forceinline__ void ldsm_x4(uint32_t* r, uint32_t addr) {
    asm volatile("ldmatrix.sync.aligned.m8n8.x4.shared.b16 {%0,%1,%2,%3}, [%4];"
                 : "=r"(r[0]), "=r"(r[1]), "=r"(r[2]), "=r"(r[3]) : "r"(addr));
}

__device__ __forceinline__ void mma_bf16(float* c, const uint32_t* a, const uint32_t* b) {
    asm volatile(
        "mma.sync.aligned.m16n8k16.row.col.f32.bf16.bf16.f32 "
        "{%0,%1,%2,%3}, {%4,%5,%6,%7}, {%8,%9}, {%0,%1,%2,%3};"
        : "+f"(c[0]), "+f"(c[1]), "+f"(c[2]), "+f"(c[3])
        : "r"(a[0]), "r"(a[1]), "r"(a[2]), "r"(a[3]), "r"(b[0]), "r"(b[1]));
}

__device__ __forceinline__ void cp_async16(uint32_t saddr, const void* gptr) {
    asm volatile("cp.async.cg.shared.global [%0], [%1], 16;" :: "r"(saddr), "l"(gptr));
}
#define CP_COMMIT() asm volatile("cp.async.commit_group;")
template <int N>
__device__ __forceinline__ void cp_wait() {
    asm volatile("cp.async.wait_group %0;" :: "n"(N));
}

__device__ __forceinline__ float2 blockReduceSum2_256(float a, float b) {
    __shared__ float sa[8], sb[8];
    int lane = threadIdx.x & 31, w = threadIdx.x >> 5;
#pragma unroll
    for (int o = 16; o; o >>= 1) {
        a += __shfl_xor_sync(0xffffffffu, a, o);
        b += __shfl_xor_sync(0xffffffffu, b, o);
    }
    if (lane == 0) { sa[w] = a; sb[w] = b; }
    __syncthreads();
    if (w == 0) {
        a = (lane < 8) ? sa[lane] : 0.f;
        b = (lane < 8) ? sb[lane] : 0.f;
#pragma unroll
        for (int o = 4; o; o >>= 1) {
            a += __shfl_xor_sync(0xffffffffu, a, o);
            b += __shfl_xor_sync(0xffffffffu, b, o);
        }
        if (lane == 0) { sa[0] = a; sb[0] = b; }
    }
    __syncthreads();
    float ra = sa[0], rb = sb[0];
    __syncthreads();
    return make_float2(ra, rb);
}

// ---------------- K1: embedding + positional LN (warp per row) ----------
__global__ void __launch_bounds__(256) embed_ln_kernel(
    const int* __restrict__ tokens, const float* __restrict__ wte,
    const float* __restrict__ wpe, const float* __restrict__ gew,
    const float* __restrict__ gpw) {
    int warp = threadIdx.x >> 5, lane = threadIdx.x & 31;
    int row = blockIdx.x * 8 + warp;
    const float* src;
    float* dst;
    const float* g;
    __nv_bfloat16* dst16 = nullptr;
    if (row < Bq * Sq) {
        int tok = __ldg(tokens + row);
        src = wte + (size_t)tok * Dq;
        dst = g_ebuf + (size_t)row * Dq;
        g = gew;
    } else {
        int s = row - Bq * Sq;
        src = wpe + (size_t)s * Dq;
        dst = g_p0buf + (size_t)s * Dq;
        dst16 = g_pA + (size_t)s * Dq;
        g = gpw;
    }
    float4 v0 = *(const float4*)(src + lane * 8);
    float4 v1 = *(const float4*)(src + lane * 8 + 4);
    float s1 = v0.x + v0.y + v0.z + v0.w + v1.x + v1.y + v1.z + v1.w;
    float s2 = v0.x * v0.x + v0.y * v0.y + v0.z * v0.z + v0.w * v0.w +
               v1.x * v1.x + v1.y * v1.y + v1.z * v1.z + v1.w * v1.w;
#pragma unroll
    for (int o = 16; o; o >>= 1) {
        s1 += __shfl_xor_sync(0xffffffffu, s1, o);
        s2 += __shfl_xor_sync(0xffffffffu, s2, o);
    }
    float mean = s1 * (1.0f / Dq);
    float var = s2 * (1.0f / Dq) - mean * mean;
    float rstd = rsqrtf(var + 1e-5f);
    float4 g0 = *(const float4*)(g + lane * 8);
    float4 g1 = *(const float4*)(g + lane * 8 + 4);
    float4 o0, o1;
    o0.x = (v0.x - mean) * rstd * g0.x;
    o0.y = (v0.y - mean) * rstd * g0.y;
    o0.z = (v0.z - mean) * rstd * g0.z;
    o0.w = (v0.w - mean) * rstd * g0.w;
    o1.x = (v1.x - mean) * rstd * g1.x;
    o1.y = (v1.y - mean) * rstd * g1.y;
    o1.z = (v1.z - mean) * rstd * g1.z;
    o1.w = (v1.w - mean) * rstd * g1.w;
    *(float4*)(dst + lane * 8) = o0;
    *(float4*)(dst + lane * 8 + 4) = o1;
    if (dst16) {
        __nv_bfloat162 b0 = __floats2bfloat162_rn(o0.x, o0.y);
        __nv_bfloat162 b1 = __floats2bfloat162_rn(o0.z, o0.w);
        __nv_bfloat162 b2 = __floats2bfloat162_rn(o1.x, o1.y);
        __nv_bfloat162 b3 = __floats2bfloat162_rn(o1.z, o1.w);
        uint4 u;
        u.x = reinterpret_cast<uint32_t&>(b0);
        u.y = reinterpret_cast<uint32_t&>(b1);
        u.z = reinterpret_cast<uint32_t&>(b2);
        u.w = reinterpret_cast<uint32_t&>(b3);
        *(uint4*)(dst16 + lane * 8) = u;
    }
}

// ---------------- prep: both weight transposes in ONE launch -------------
__device__ __forceinline__ void do_transpose(const float* __restrict__ src,
                                             __nv_bfloat16* __restrict__ dst,
                                             int R, int C, int bx, int by) {
    __shared__ float t[32][33];
    int c0 = bx * 32, r0 = by * 32;
    int x = threadIdx.x, y = threadIdx.y;
#pragma unroll
    for (int i = 0; i < 32; i += 8) t[y + i][x] = src[(size_t)(r0 + y + i) * C + c0 + x];
    __syncthreads();
#pragma unroll
    for (int i = 0; i < 32; i += 8)
        dst[(size_t)(c0 + y + i) * R + r0 + x] = __float2bfloat16(t[x][y + i]);
}

__global__ void transpose_both_kernel(const float* __restrict__ w1,
                                      const float* __restrict__ w2) {
    int bid = blockIdx.x;
    if (bid < 256) {
        // ff_w1: R=Dq(256), C=Hq(1024): grid 32 x 8
        do_transpose(w1, g_w1t, Dq, Hq, bid & 31, bid >> 5);
    } else {
        bid -= 256;
        // ff_w2: R=Hq(1024), C=Dq(256): grid 8 x 32
        do_transpose(w2, g_w2t, Hq, Dq, bid & 7, bid >> 3);
    }
}

// ---------------- FFN GEMMs: mma.sync + 3-stage cp.async pipeline --------
// MODE 0: h = gelu(p_raw @ ff_w1), BM=128: warps 4x2, warp tile 32x32
// MODE 1: p = p_raw + h @ ff_w2,   BM=64:  warps 2x4, warp tile 32x16
template <int BM, int WMc, int WNc, int MODE>
__global__ void __launch_bounds__(256) ffn_mma_kernel() {
    constexpr int BN = 64, BK = 64, LDS = 72, ST = 3;
    constexpr int Kd = (MODE == 0) ? Dq : Hq;
    constexpr int Nd = (MODE == 0) ? Hq : Dq;
    constexpr int NCH = Kd / BK;
    constexpr int wtM = BM / WMc, wtN = BN / WNc;
    constexpr int MT = wtM / 16, NT = wtN / 16;
    const __nv_bfloat16* __restrict__ A = (MODE == 0) ? g_pA : g_hbf;
    const __nv_bfloat16* __restrict__ Bt = (MODE == 0) ? g_w1t : g_w2t;

    extern __shared__ __nv_bfloat16 dynsm[];
    __nv_bfloat16* AsBase = dynsm;                     // ST x BM x LDS
    __nv_bfloat16* BsBase = dynsm + ST * BM * LDS;     // ST x BN x LDS

    int tid = threadIdx.x, wid = tid >> 5, lane = tid & 31;
    int warp_m = wid % WMc, warp_n = wid / WMc;
    int m0 = blockIdx.y * BM, n0 = blockIdx.x * BN;

    int a_row = warp_m * wtM + ((lane >> 3) & 1) * 8 + (lane & 7);
    int a_col = (lane >> 4) * 8;
    int b_row = warp_n * wtN + ((lane >> 4) & 1) * 8 + (lane & 7);
    int b_col = ((lane >> 3) & 1) * 8;

    auto load_stage = [&](int st, int k0) {
        __nv_bfloat16* As = AsBase + st * BM * LDS;
        __nv_bfloat16* Bs = BsBase + st * BN * LDS;
        constexpr int CA = BM * 8 / 256;
#pragma unroll
        for (int i = 0; i < CA; i++) {
            int id = tid + i * 256;
            int r = id >> 3, cc = (id & 7) * 8;
            cp_async16(smem_u32(As + r * LDS + cc), A + (size_t)(m0 + r) * Kd + k0 + cc);
        }
        constexpr int CB = BN * 8 / 256;
#pragma unroll
        for (int i = 0; i < CB; i++) {
            int id = tid + i * 256;
            int r = id >> 3, cc = (id & 7) * 8;
            cp_async16(smem_u32(Bs + r * LDS + cc), Bt + (size_t)(n0 + r) * Kd + k0 + cc);
        }
        CP_COMMIT();
    };

    float c[MT][NT * 2][4] = {};

    load_stage(0, 0);
    load_stage(1, BK);
    for (int ch = 0; ch < NCH; ch++) {
        if (ch == NCH - 1) cp_wait<0>(); else cp_wait<1>();
        __syncthreads();
        if (ch + 2 < NCH) load_stage((ch + 2) % ST, (ch + 2) * BK);
        int st = ch % ST;
        uint32_t As_base = smem_u32(AsBase + st * BM * LDS);
        uint32_t Bs_base = smem_u32(BsBase + st * BN * LDS);
#pragma unroll
        for (int kk = 0; kk < BK / 16; kk++) {
            uint32_t a[MT][4], b[NT][4];
#pragma unroll
            for (int mt = 0; mt < MT; mt++)
                ldsm_x4(a[mt], As_base + ((a_row + mt * 16) * LDS + kk * 16 + a_col) * 2);
#pragma unroll
            for (int nt = 0; nt < NT; nt++)
                ldsm_x4(b[nt], Bs_base + ((b_row + nt * 16) * LDS + kk * 16 + b_col) * 2);
#pragma unroll
            for (int mt = 0; mt < MT; mt++)
#pragma unroll
                for (int nt = 0; nt < NT; nt++) {
                    mma_bf16(c[mt][nt * 2 + 0], a[mt], &b[nt][0]);
                    mma_bf16(c[mt][nt * 2 + 1], a[mt], &b[nt][2]);
                }
        }
    }

    // epilogue
    int group = lane >> 2, tg = lane & 3;
#pragma unroll
    for (int mt = 0; mt < MT; mt++) {
#pragma unroll
        for (int nt = 0; nt < NT * 2; nt++) {
#pragma unroll
            for (int half = 0; half < 2; half++) {
                int m = m0 + warp_m * wtM + mt * 16 + group + half * 8;
                int n = n0 + warp_n * wtN + nt * 8 + tg * 2;
                float v0 = c[mt][nt][half * 2 + 0];
                float v1 = c[mt][nt][half * 2 + 1];
                if (MODE == 0) {
                    v0 = 0.5f * v0 * (1.0f + erff(v0 * 0.70710678118654752f));
                    v1 = 0.5f * v1 * (1.0f + erff(v1 * 0.70710678118654752f));
                    __nv_bfloat162 h = __floats2bfloat162_rn(v0, v1);
                    *(uint32_t*)&g_hbf[(size_t)m * Nd + n] = reinterpret_cast<uint32_t&>(h);
                } else {
                    float2 r = *(const float2*)(g_p0buf + (size_t)m * Nd + n);
                    float2 o = make_float2(v0 + r.x, v1 + r.y);
                    *(float2*)(g_pbuf + (size_t)m * Nd + n) = o;
                }
            }
        }
    }
}

// ---------------- K4a: partial q = Wq^T p_last ----------------
__global__ void qk_q_kernel(const float* __restrict__ Wq) {
    int l = blockIdx.x, c = blockIdx.y;
    int j = threadIdx.x;
    __shared__ float pl[32];
    if (j < 32) pl[j] = g_pbuf[(size_t)(Sq - 1) * Dq + c * 32 + j];
    __syncthreads();
    const float* wq = Wq + (size_t)l * Dq * Dq + (size_t)c * 32 * Dq;
    float acc = 0.f;
#pragma unroll
    for (int i = 0; i < 32; i++) acc += pl[i] * wq[(size_t)i * Dq + j];
    g_qpart[(l * 8 + c) * Dq + j] = acc;
}

// ---------------- K4b: m_l = Wk_l @ q_l ----------------
__global__ void qk_m_kernel(const float* __restrict__ Wk) {
    int l = blockIdx.x;
    int tid = threadIdx.x;
    int warp = tid >> 5, lane = tid & 31;
    __shared__ float qs[Dq];
    {
        float acc = 0.f;
#pragma unroll
        for (int c = 0; c < 8; c++) acc += g_qpart[(l * 8 + c) * Dq + tid];
        qs[tid] = acc;
    }
    __syncthreads();
    int j = blockIdx.y * 8 + warp;
    const float* wk = Wk + (size_t)l * Dq * Dq + (size_t)j * Dq;
    float m = 0.f;
#pragma unroll
    for (int i = 0; i < 8; i++) {
        int idx = lane + i * 32;
        m += wk[idx] * qs[idx];
    }
#pragma unroll
    for (int o = 16; o; o >>= 1) m += __shfl_xor_sync(0xffffffffu, m, o);
    if (lane == 0) g_mbuf[l * Dq + j] = m;
}

// ---------------- K5: scores, single pass over p for all 6 layers --------
__global__ void score_kernel() {
    int warp = threadIdx.x >> 5, lane = threadIdx.x & 31;
    int t = blockIdx.x * 8 + warp;
    const float* p = g_pbuf + (size_t)t * Dq;
    float pv[8];
#pragma unroll
    for (int i = 0; i < 8; i++) pv[i] = p[lane + i * 32];
    float acc[Lq];
#pragma unroll
    for (int l = 0; l < Lq; l++) {
        const float* m = g_mbuf + l * Dq;
        float a = 0.f;
#pragma unroll
        for (int i = 0; i < 8; i++) a += pv[i] * __ldg(m + lane + i * 32);
        acc[l] = a;
    }
#pragma unroll
    for (int l = 0; l < Lq; l++) {
#pragma unroll
        for (int o = 16; o; o >>= 1) acc[l] += __shfl_xor_sync(0xffffffffu, acc[l], o);
    }
    if (lane == 0) {
#pragma unroll
        for (int l = 0; l < Lq; l++) g_sbuf[l * Sq + t] = acc[l] * 0.0625f;
    }
}

// ---------------- K6: softmax ----------------
__global__ void softmax_kernel() {
    int l = blockIdx.x;
    int tid = threadIdx.x;
    __shared__ float red[32];
    __shared__ float bc;
    float v[4];
    float mx = -1e30f;
#pragma unroll
    for (int i = 0; i < 4; i++) {
        v[i] = g_sbuf[l * Sq + tid + i * 1024];
        mx = fmaxf(mx, v[i]);
    }
#pragma unroll
    for (int o = 16; o; o >>= 1) mx = fmaxf(mx, __shfl_xor_sync(0xffffffffu, mx, o));
    if ((tid & 31) == 0) red[tid >> 5] = mx;
    __syncthreads();
    if (tid < 32) {
        float m = red[tid];
#pragma unroll
        for (int o = 16; o; o >>= 1) m = fmaxf(m, __shfl_xor_sync(0xffffffffu, m, o));
        if (tid == 0) bc = m;
    }
    __syncthreads();
    float M = bc;
    float sum = 0.f;
#pragma unroll
    for (int i = 0; i < 4; i++) {
        v[i] = expf(v[i] - M);
        sum += v[i];
    }
#pragma unroll
    for (int o = 16; o; o >>= 1) sum += __shfl_xor_sync(0xffffffffu, sum, o);
    __syncthreads();
    if ((tid & 31) == 0) red[tid >> 5] = sum;
    __syncthreads();
    if (tid < 32) {
        float s2 = red[tid];
#pragma unroll
        for (int o = 16; o; o >>= 1) s2 += __shfl_xor_sync(0xffffffffu, s2, o);
        if (tid == 0) bc = s2;
    }
    __syncthreads();
    float inv = 1.0f / bc;
#pragma unroll
    for (int i = 0; i < 4; i++) g_abuf[l * Sq + tid + i * 1024] = v[i] * inv;
}

// ---------------- K7: ctx partials ----------------
__global__ void ctx_kernel() {
    int chunk = blockIdx.x;
    int b = blockIdx.y;
    int d = threadIdx.x;
    __shared__ float as_[Lq][128];
    for (int i = d; i < Lq * 128; i += 256) {
        int l = i >> 7, t = i & 127;
        as_[l][t] = g_abuf[l * Sq + chunk * 128 + t];
    }
    __syncthreads();
    float acc[Lq] = {};
    const float* ep = g_ebuf + ((size_t)b * Sq + (size_t)chunk * 128) * Dq + d;
#pragma unroll 4
    for (int t = 0; t < 128; t++) {
        float ev = ep[(size_t)t * Dq];
#pragma unroll
        for (int l = 0; l < Lq; l++) acc[l] += as_[l][t] * ev;
    }
#pragma unroll
    for (int l = 0; l < Lq; l++)
        g_ctxpart[(((size_t)chunk * Lq + l) * Bq + b) * Dq + d] = acc[l];
}

// ---------------- K9: Wv projection (fused partial reduce) ---------------
__global__ void vproj_kernel(const float* __restrict__ Wv) {
    int l = blockIdx.x, b = blockIdx.y, d = threadIdx.x;
    __shared__ float c[Dq];
    float acc = 0.f;
#pragma unroll
    for (int ch = 0; ch < 32; ch++)
        acc += g_ctxpart[(((size_t)ch * Lq + l) * Bq + b) * Dq + d];
    c[d] = acc;
    __syncthreads();
    const float* wv = Wv + (size_t)l * Dq * Dq;
    float o = 0.f;
#pragma unroll 4
    for (int k = 0; k < Dq; k++) o += c[k] * wv[(size_t)k * Dq + d];
    g_attnout[((size_t)l * Bq + b) * Dq + d] = o;
}

// ---------------- K10: final LN ----------------
__global__ void final_ln_kernel(const float* __restrict__ g_out_w) {
    int b = blockIdx.x, d = threadIdx.x;
    float x = g_ebuf[((size_t)b * Sq + Sq - 1) * Dq + d] + g_p0buf[(size_t)(Sq - 1) * Dq + d];
#pragma unroll
    for (int l = 0; l < Lq; l++) x += g_attnout[((size_t)l * Bq + b) * Dq + d];
    float2 r = blockReduceSum2_256(x, x * x);
    float mean = r.x * (1.0f / Dq);
    float var = r.y * (1.0f / Dq) - mean * mean;
    g_xhat[b * Dq + d] = (x - mean) * rsqrtf(var + 1e-5f) * g_out_w[d];
}

// ---------------- K11: logits ----------------
__global__ void logits_kernel(const float* __restrict__ wte,
                              const float* __restrict__ gew,
                              float* __restrict__ out) {
    __shared__ float xs[Bq * Dq];
    __shared__ float gs[Dq];
    int tid = threadIdx.x;
    for (int i = tid; i < Bq * Dq; i += 256) xs[i] = g_xhat[i];
    gs[tid] = gew[tid];
    __syncthreads();
    int warp = tid >> 5, lane = tid & 31;
    int v = blockIdx.x * 8 + warp;
    const float* w = wte + (size_t)v * Dq;
    float wv[8];
    float s = 0.f, ss = 0.f;
#pragma unroll
    for (int i = 0; i < 8; i++) {
        wv[i] = w[lane + i * 32];
        s += wv[i];
        ss += wv[i] * wv[i];
    }
#pragma unroll
    for (int o = 16; o; o >>= 1) {
        s += __shfl_xor_sync(0xffffffffu, s, o);
        ss += __shfl_xor_sync(0xffffffffu, ss, o);
    }
    float mean = s * (1.0f / Dq);
    float var = ss * (1.0f / Dq) - mean * mean;
    float rstd = rsqrtf(var + 1e-5f);
    float wn[8];
#pragma unroll
    for (int i = 0; i < 8; i++) wn[i] = (wv[i] - mean) * rstd * gs[lane + i * 32];
#pragma unroll
    for (int b = 0; b < Bq; b++) {
        float dot = 0.f;
#pragma unroll
        for (int i = 0; i < 8; i++) dot += wn[i] * xs[b * Dq + lane + i * 32];
#pragma unroll
        for (int o = 16; o; o >>= 1) dot += __shfl_xor_sync(0xffffffffu, dot, o);
        if (lane == 0) out[(size_t)b * Vq + v] = dot;
    }
}

// ---------------- launch ----------------
extern "C" void kernel_launch(void* const* d_in, const int* in_sizes, int n_in,
                              void* d_out, int out_size) {
    const int* tokens = (const int*)d_in[0];
    const float* wte = (const float*)d_in[1];
    const float* wpe = (const float*)d_in[2];
    const float* g_e = (const float*)d_in[3];
    const float* g_p = (const float*)d_in[4];
    const float* g_out = (const float*)d_in[5];
    const float* ff_w1 = (const float*)d_in[6];
    const float* ff_w2 = (const float*)d_in[7];
    const float* Wq = (const float*)d_in[8];
    const float* Wk = (const float*)d_in[9];
    const float* Wv = (const float*)d_in[10];
    float* out = (float*)d_out;

    constexpr int SM0 = 3 * (128 + 64) * 72 * 2;  // 82944 B
    constexpr int SM1 = 3 * (64 + 64) * 72 * 2;   // 55296 B
    cudaFuncSetAttribute(ffn_mma_kernel<128, 4, 2, 0>,
                         cudaFuncAttributeMaxDynamicSharedMemorySize, SM0);
    cudaFuncSetAttribute(ffn_mma_kernel<64, 2, 4, 1>,
                         cudaFuncAttributeMaxDynamicSharedMemorySize, SM1);

    // weight transposes (one launch)
    transpose_both_kernel<<<512, dim3(32, 8)>>>(ff_w1, ff_w2);
    // 1. embeddings + positional LN (+ fused bf16 p_raw)
    embed_ln_kernel<<<(Bq * Sq + Sq) / 8, 256>>>(tokens, wte, wpe, g_e, g_p);
    // 2/3. FFN on tensor cores (3-stage pipelined)
    ffn_mma_kernel<128, 4, 2, 0><<<dim3(Hq / 64, Sq / 128), 256, SM0>>>();
    ffn_mma_kernel<64, 2, 4, 1><<<dim3(Dq / 64, Sq / 64), 256, SM1>>>();
    // 4. per-layer score direction m_l
    qk_q_kernel<<<dim3(Lq, 8), 256>>>(Wq);
    qk_m_kernel<<<dim3(Lq, 32), 256>>>(Wk);
    // 5. scores (all 6 layers, one pass over p)
    score_kernel<<<Sq / 8, 256>>>();
    // 6. softmax
    softmax_kernel<<<Lq, 1024>>>();
    // 7. ctx partials
    ctx_kernel<<<dim3(32, Bq), 256>>>();
    // 8. Wv projection (+ fused reduce)
    vproj_kernel<<<dim3(Lq, Bq), 256>>>(Wv);
    // 9. final LN
    final_ln_kernel<<<Bq, 256>>>(g_out);
    // 10. logits
    logits_kernel<<<Vq / 8, 256>>>(wte, g_e, out);
}

// round 7
// speedup vs baseline: 2.7111x; 1.0150x over previous
#include <cuda_runtime.h>
#include <cuda_bf16.h>
#include <math.h>
#include <stdint.h>

#define Bq 4
#define Sq 4096
#define Dq 256
#define Lq 6
#define Vq 32000
#define Hq 1024

// ---------------- scratch (no allocations allowed) ----------------
__device__ float g_ebuf[(size_t)Bq * Sq * Dq];   // e = ln(wte[tokens])        16MB
__device__ float g_p0buf[Sq * Dq];               // p_raw = ln(wpe[:S])         4MB
__device__ float g_pbuf[Sq * Dq];                // p (post-FFN, fp32)          4MB
__device__ __nv_bfloat16 g_pA[Sq * Dq];          // bf16(p_raw)                 2MB
__device__ __nv_bfloat16 g_hbf[(size_t)Sq * Hq]; // bf16 FFN hidden             8MB
__device__ __nv_bfloat16 g_w1t[Hq * Dq];         // ff_w1^T  [H][D] bf16
__device__ __nv_bfloat16 g_w2t[Dq * Hq];         // ff_w2^T  [D][H] bf16
__device__ float g_qpart[Lq * 8 * Dq];
__device__ float g_mbuf[Lq * Dq];
__device__ float g_abuf[Lq * Sq];                // exp(scores), unnormalized
__device__ float g_asum[32 * Lq];                // per-chunk sum of exp
__device__ float g_ctxpart[32 * Lq * Bq * Dq];
__device__ float g_attnout[Lq * Bq * Dq];
__device__ float g_xhat[Bq * Dq];

// ---------------- helpers ----------------
__device__ __forceinline__ uint32_t smem_u32(const void* p) {
    uint32_t a;
    asm("{ .reg .u64 t; cvta.to.shared.u64 t, %1; cvt.u32.u64 %0, t; }" : "=r"(a) : "l"(p));
    return a;
}

__device__ __forceinline__ void ldsm_x4(uint32_t* r, uint32_t addr) {
    asm volatile("ldmatrix.sync.aligned.m8n8.x4.shared.b16 {%0,%1,%2,%3}, [%4];"
                 : "=r"(r[0]), "=r"(r[1]), "=r"(r[2]), "=r"(r[3]) : "r"(addr));
}

__device__ __forceinline__ void mma_bf16(float* c, const uint32_t* a, const uint32_t* b) {
    asm volatile(
        "mma.sync.aligned.m16n8k16.row.col.f32.bf16.bf16.f32 "
        "{%0,%1,%2,%3}, {%4,%5,%6,%7}, {%8,%9}, {%0,%1,%2,%3};"
        : "+f"(c[0]), "+f"(c[1]), "+f"(c[2]), "+f"(c[3])
        : "r"(a[0]), "r"(a[1]), "r"(a[2]), "r"(a[3]), "r"(b[0]), "r"(b[1]));
}

__device__ __forceinline__ void cp_async16(uint32_t saddr, const void* gptr) {
    asm volatile("cp.async.cg.shared.global [%0], [%1], 16;" :: "r"(saddr), "l"(gptr));
}
#define CP_COMMIT() asm volatile("cp.async.commit_group;")
template <int N>
__device__ __forceinline__ void cp_wait() {
    asm volatile("cp.async.wait_group %0;" :: "n"(N));
}

__device__ __forceinline__ float2 blockReduceSum2_256(float a, float b) {
    __shared__ float sa[8], sb[8];
    int lane = threadIdx.x & 31, w = threadIdx.x >> 5;
#pragma unroll
    for (int o = 16; o; o >>= 1) {
        a += __shfl_xor_sync(0xffffffffu, a, o);
        b += __shfl_xor_sync(0xffffffffu, b, o);
    }
    if (lane == 0) { sa[w] = a; sb[w] = b; }
    __syncthreads();
    if (w == 0) {
        a = (lane < 8) ? sa[lane] : 0.f;
        b = (lane < 8) ? sb[lane] : 0.f;
#pragma unroll
        for (int o = 4; o; o >>= 1) {
            a += __shfl_xor_sync(0xffffffffu, a, o);
            b += __shfl_xor_sync(0xffffffffu, b, o);
        }
        if (lane == 0) { sa[0] = a; sb[0] = b; }
    }
    __syncthreads();
    float ra = sa[0], rb = sb[0];
    __syncthreads();
    return make_float2(ra, rb);
}

// ---------------- K1: embedding + positional LN (warp per row) ----------
__global__ void __launch_bounds__(256) embed_ln_kernel(
    const int* __restrict__ tokens, const float* __restrict__ wte,
    const float* __restrict__ wpe, const float* __restrict__ gew,
    const float* __restrict__ gpw) {
    int warp = threadIdx.x >> 5, lane = threadIdx.x & 31;
    int row = blockIdx.x * 8 + warp;
    const float* src;
    float* dst;
    const float* g;
    __nv_bfloat16* dst16 = nullptr;
    if (row < Bq * Sq) {
        int tok = __ldg(tokens + row);
        src = wte + (size_t)tok * Dq;
        dst = g_ebuf + (size_t)row * Dq;
        g = gew;
    } else {
        int s = row - Bq * Sq;
        src = wpe + (size_t)s * Dq;
        dst = g_p0buf + (size_t)s * Dq;
        dst16 = g_pA + (size_t)s * Dq;
        g = gpw;
    }
    float4 v0 = *(const float4*)(src + lane * 8);
    float4 v1 = *(const float4*)(src + lane * 8 + 4);
    float s1 = v0.x + v0.y + v0.z + v0.w + v1.x + v1.y + v1.z + v1.w;
    float s2 = v0.x * v0.x + v0.y * v0.y + v0.z * v0.z + v0.w * v0.w +
               v1.x * v1.x + v1.y * v1.y + v1.z * v1.z + v1.w * v1.w;
#pragma unroll
    for (int o = 16; o; o >>= 1) {
        s1 += __shfl_xor_sync(0xffffffffu, s1, o);
        s2 += __shfl_xor_sync(0xffffffffu, s2, o);
    }
    float mean = s1 * (1.0f / Dq);
    float var = s2 * (1.0f / Dq) - mean * mean;
    float rstd = rsqrtf(var + 1e-5f);
    float4 g0 = *(const float4*)(g + lane * 8);
    float4 g1 = *(const float4*)(g + lane * 8 + 4);
    float4 o0, o1;
    o0.x = (v0.x - mean) * rstd * g0.x;
    o0.y = (v0.y - mean) * rstd * g0.y;
    o0.z = (v0.z - mean) * rstd * g0.z;
    o0.w = (v0.w - mean) * rstd * g0.w;
    o1.x = (v1.x - mean) * rstd * g1.x;
    o1.y = (v1.y - mean) * rstd * g1.y;
    o1.z = (v1.z - mean) * rstd * g1.z;
    o1.w = (v1.w - mean) * rstd * g1.w;
    *(float4*)(dst + lane * 8) = o0;
    *(float4*)(dst + lane * 8 + 4) = o1;
    if (dst16) {
        __nv_bfloat162 b0 = __floats2bfloat162_rn(o0.x, o0.y);
        __nv_bfloat162 b1 = __floats2bfloat162_rn(o0.z, o0.w);
        __nv_bfloat162 b2 = __floats2bfloat162_rn(o1.x, o1.y);
        __nv_bfloat162 b3 = __floats2bfloat162_rn(o1.z, o1.w);
        uint4 u;
        u.x = reinterpret_cast<uint32_t&>(b0);
        u.y = reinterpret_cast<uint32_t&>(b1);
        u.z = reinterpret_cast<uint32_t&>(b2);
        u.w = reinterpret_cast<uint32_t&>(b3);
        *(uint4*)(dst16 + lane * 8) = u;
    }
}

// ---------------- prep: both weight transposes in ONE launch -------------
__device__ __forceinline__ void do_transpose(const float* __restrict__ src,
                                             __nv_bfloat16* __restrict__ dst,
                                             int R, int C, int bx, int by) {
    __shared__ float t[32][33];
    int c0 = bx * 32, r0 = by * 32;
    int x = threadIdx.x, y = threadIdx.y;
#pragma unroll
    for (int i = 0; i < 32; i += 8) t[y + i][x] = src[(size_t)(r0 + y + i) * C + c0 + x];
    __syncthreads();
#pragma unroll
    for (int i = 0; i < 32; i += 8)
        dst[(size_t)(c0 + y + i) * R + r0 + x] = __float2bfloat16(t[x][y + i]);
}

__global__ void transpose_both_kernel(const float* __restrict__ w1,
                                      const float* __restrict__ w2) {
    int bid = blockIdx.x;
    if (bid < 256) {
        do_transpose(w1, g_w1t, Dq, Hq, bid & 31, bid >> 5);
    } else {
        bid -= 256;
        do_transpose(w2, g_w2t, Hq, Dq, bid & 7, bid >> 3);
    }
}

// ---------------- FFN GEMMs: mma.sync, 4 warps, big warp tiles -----------
// MODE 0: h = gelu(p_raw @ ff_w1), BM=128, warp 64x32 (MT=4): grid (16,32)
// MODE 1: p = p_raw + h @ ff_w2,   BM=64,  warp 32x32 (MT=2): grid (4,64)
template <int BM, int WT_M, int MODE>
__global__ void __launch_bounds__(128) ffn_mma_kernel() {
    constexpr int BN = 64, BK = 64, LDS = 72, ST = 3;
    constexpr int Kd = (MODE == 0) ? Dq : Hq;
    constexpr int Nd = (MODE == 0) ? Hq : Dq;
    constexpr int NCH = Kd / BK;
    constexpr int wtM = WT_M, wtN = 32;
    constexpr int MT = wtM / 16, NT = wtN / 16;
    const __nv_bfloat16* __restrict__ A = (MODE == 0) ? g_pA : g_hbf;
    const __nv_bfloat16* __restrict__ Bt = (MODE == 0) ? g_w1t : g_w2t;

    extern __shared__ __nv_bfloat16 dynsm[];
    __nv_bfloat16* AsBase = dynsm;                     // ST x BM x LDS
    __nv_bfloat16* BsBase = dynsm + ST * BM * LDS;     // ST x BN x LDS

    int tid = threadIdx.x, wid = tid >> 5, lane = tid & 31;
    int warp_m = wid & 1, warp_n = wid >> 1;
    int m0 = blockIdx.y * BM, n0 = blockIdx.x * BN;

    int a_row = warp_m * wtM + ((lane >> 3) & 1) * 8 + (lane & 7);
    int a_col = (lane >> 4) * 8;
    int b_row = warp_n * wtN + ((lane >> 4) & 1) * 8 + (lane & 7);
    int b_col = ((lane >> 3) & 1) * 8;

    auto load_stage = [&](int st, int k0) {
        __nv_bfloat16* As = AsBase + st * BM * LDS;
        __nv_bfloat16* Bs = BsBase + st * BN * LDS;
        constexpr int CA = BM * 8 / 128;
#pragma unroll
        for (int i = 0; i < CA; i++) {
            int id = tid + i * 128;
            int r = id >> 3, cc = (id & 7) * 8;
            cp_async16(smem_u32(As + r * LDS + cc), A + (size_t)(m0 + r) * Kd + k0 + cc);
        }
        constexpr int CB = BN * 8 / 128;
#pragma unroll
        for (int i = 0; i < CB; i++) {
            int id = tid + i * 128;
            int r = id >> 3, cc = (id & 7) * 8;
            cp_async16(smem_u32(Bs + r * LDS + cc), Bt + (size_t)(n0 + r) * Kd + k0 + cc);
        }
        CP_COMMIT();
    };

    float c[MT][NT * 2][4] = {};

    load_stage(0, 0);
    load_stage(1, BK);
    for (int ch = 0; ch < NCH; ch++) {
        if (ch == NCH - 1) cp_wait<0>(); else cp_wait<1>();
        __syncthreads();
        if (ch + 2 < NCH) load_stage((ch + 2) % ST, (ch + 2) * BK);
        int st = ch % ST;
        uint32_t As_base = smem_u32(AsBase + st * BM * LDS);
        uint32_t Bs_base = smem_u32(BsBase + st * BN * LDS);
#pragma unroll
        for (int kk = 0; kk < BK / 16; kk++) {
            uint32_t a[MT][4], b[NT][4];
#pragma unroll
            for (int mt = 0; mt < MT; mt++)
                ldsm_x4(a[mt], As_base + ((a_row + mt * 16) * LDS + kk * 16 + a_col) * 2);
#pragma unroll
            for (int nt = 0; nt < NT; nt++)
                ldsm_x4(b[nt], Bs_base + ((b_row + nt * 16) * LDS + kk * 16 + b_col) * 2);
#pragma unroll
            for (int mt = 0; mt < MT; mt++)
#pragma unroll
                for (int nt = 0; nt < NT; nt++) {
                    mma_bf16(c[mt][nt * 2 + 0], a[mt], &b[nt][0]);
                    mma_bf16(c[mt][nt * 2 + 1], a[mt], &b[nt][2]);
                }
        }
    }

    // epilogue
    int group = lane >> 2, tg = lane & 3;
#pragma unroll
    for (int mt = 0; mt < MT; mt++) {
#pragma unroll
        for (int nt = 0; nt < NT * 2; nt++) {
#pragma unroll
            for (int half = 0; half < 2; half++) {
                int m = m0 + warp_m * wtM + mt * 16 + group + half * 8;
                int n = n0 + warp_n * wtN + nt * 8 + tg * 2;
                float v0 = c[mt][nt][half * 2 + 0];
                float v1 = c[mt][nt][half * 2 + 1];
                if (MODE == 0) {
                    v0 = 0.5f * v0 * (1.0f + erff(v0 * 0.70710678118654752f));
                    v1 = 0.5f * v1 * (1.0f + erff(v1 * 0.70710678118654752f));
                    __nv_bfloat162 h = __floats2bfloat162_rn(v0, v1);
                    *(uint32_t*)&g_hbf[(size_t)m * Nd + n] = reinterpret_cast<uint32_t&>(h);
                } else {
                    float2 r = *(const float2*)(g_p0buf + (size_t)m * Nd + n);
                    float2 o = make_float2(v0 + r.x, v1 + r.y);
                    *(float2*)(g_pbuf + (size_t)m * Nd + n) = o;
                }
            }
        }
    }
}

// ---------------- K4a: partial q = Wq^T p_last ----------------
__global__ void qk_q_kernel(const float* __restrict__ Wq) {
    int l = blockIdx.x, c = blockIdx.y;
    int j = threadIdx.x;
    __shared__ float pl[32];
    if (j < 32) pl[j] = g_pbuf[(size_t)(Sq - 1) * Dq + c * 32 + j];
    __syncthreads();
    const float* wq = Wq + (size_t)l * Dq * Dq + (size_t)c * 32 * Dq;
    float acc = 0.f;
#pragma unroll
    for (int i = 0; i < 32; i++) acc += pl[i] * wq[(size_t)i * Dq + j];
    g_qpart[(l * 8 + c) * Dq + j] = acc;
}

// ---------------- K4b: m_l = Wk_l @ q_l ----------------
__global__ void qk_m_kernel(const float* __restrict__ Wk) {
    int l = blockIdx.x;
    int tid = threadIdx.x;
    int warp = tid >> 5, lane = tid & 31;
    __shared__ float qs[Dq];
    {
        float acc = 0.f;
#pragma unroll
        for (int c = 0; c < 8; c++) acc += g_qpart[(l * 8 + c) * Dq + tid];
        qs[tid] = acc;
    }
    __syncthreads();
    int j = blockIdx.y * 8 + warp;
    const float* wk = Wk + (size_t)l * Dq * Dq + (size_t)j * Dq;
    float m = 0.f;
#pragma unroll
    for (int i = 0; i < 8; i++) {
        int idx = lane + i * 32;
        m += wk[idx] * qs[idx];
    }
#pragma unroll
    for (int o = 16; o; o >>= 1) m += __shfl_xor_sync(0xffffffffu, m, o);
    if (lane == 0) g_mbuf[l * Dq + j] = m;
}

// ---------------- K5: scores -> exp (no separate softmax) ----------------
// scores are O(1): exp without max-subtraction is safe in fp32; the
// normalization is folded into vproj via per-chunk sums from ctx_kernel.
__global__ void score_kernel() {
    int warp = threadIdx.x >> 5, lane = threadIdx.x & 31;
    int t = blockIdx.x * 8 + warp;
    const float* p = g_pbuf + (size_t)t * Dq;
    float pv[8];
#pragma unroll
    for (int i = 0; i < 8; i++) pv[i] = p[lane + i * 32];
    float acc[Lq];
#pragma unroll
    for (int l = 0; l < Lq; l++) {
        const float* m = g_mbuf + l * Dq;
        float a = 0.f;
#pragma unroll
        for (int i = 0; i < 8; i++) a += pv[i] * __ldg(m + lane + i * 32);
        acc[l] = a;
    }
#pragma unroll
    for (int l = 0; l < Lq; l++) {
#pragma unroll
        for (int o = 16; o; o >>= 1) acc[l] += __shfl_xor_sync(0xffffffffu, acc[l], o);
    }
    if (lane == 0) {
#pragma unroll
        for (int l = 0; l < Lq; l++) g_abuf[l * Sq + t] = expf(acc[l] * 0.0625f);
    }
}

// ---------------- K7: ctx partials + per-chunk exp sums ------------------
__global__ void ctx_kernel() {
    int chunk = blockIdx.x;
    int b = blockIdx.y;
    int d = threadIdx.x;
    __shared__ float as_[Lq][128];
    for (int i = d; i < Lq * 128; i += 256) {
        int l = i >> 7, t = i & 127;
        as_[l][t] = g_abuf[l * Sq + chunk * 128 + t];
    }
    __syncthreads();
    float acc[Lq] = {};
    const float* ep = g_ebuf + ((size_t)b * Sq + (size_t)chunk * 128) * Dq + d;
#pragma unroll 4
    for (int t = 0; t < 128; t++) {
        float ev = ep[(size_t)t * Dq];
#pragma unroll
        for (int l = 0; l < Lq; l++) acc[l] += as_[l][t] * ev;
    }
#pragma unroll
    for (int l = 0; l < Lq; l++)
        g_ctxpart[(((size_t)chunk * Lq + l) * Bq + b) * Dq + d] = acc[l];
    // chunk sums (once per chunk, written by b==0 block)
    if (b == 0 && d < Lq) {
        float s = 0.f;
#pragma unroll 8
        for (int t = 0; t < 128; t++) s += as_[d][t];
        g_asum[chunk * Lq + d] = s;
    }
}

// ---------------- K9: Wv projection (fused reduce + normalize) -----------
__global__ void vproj_kernel(const float* __restrict__ Wv) {
    int l = blockIdx.x, b = blockIdx.y, d = threadIdx.x;
    __shared__ float c[Dq];
    float acc = 0.f;
#pragma unroll
    for (int ch = 0; ch < 32; ch++)
        acc += g_ctxpart[(((size_t)ch * Lq + l) * Bq + b) * Dq + d];
    float ssum = 0.f;
#pragma unroll
    for (int ch = 0; ch < 32; ch++) ssum += g_asum[ch * Lq + l];
    c[d] = acc * (1.0f / ssum);
    __syncthreads();
    const float* wv = Wv + (size_t)l * Dq * Dq;
    float o = 0.f;
#pragma unroll 4
    for (int k = 0; k < Dq; k++) o += c[k] * wv[(size_t)k * Dq + d];
    g_attnout[((size_t)l * Bq + b) * Dq + d] = o;
}

// ---------------- K10: final LN ----------------
__global__ void final_ln_kernel(const float* __restrict__ g_out_w) {
    int b = blockIdx.x, d = threadIdx.x;
    float x = g_ebuf[((size_t)b * Sq + Sq - 1) * Dq + d] + g_p0buf[(size_t)(Sq - 1) * Dq + d];
#pragma unroll
    for (int l = 0; l < Lq; l++) x += g_attnout[((size_t)l * Bq + b) * Dq + d];
    float2 r = blockReduceSum2_256(x, x * x);
    float mean = r.x * (1.0f / Dq);
    float var = r.y * (1.0f / Dq) - mean * mean;
    g_xhat[b * Dq + d] = (x - mean) * rsqrtf(var + 1e-5f) * g_out_w[d];
}

// ---------------- K11: logits ----------------
__global__ void logits_kernel(const float* __restrict__ wte,
                              const float* __restrict__ gew,
                              float* __restrict__ out) {
    __shared__ float xs[Bq * Dq];
    __shared__ float gs[Dq];
    int tid = threadIdx.x;
    for (int i = tid; i < Bq * Dq; i += 256) xs[i] = g_xhat[i];
    gs[tid] = gew[tid];
    __syncthreads();
    int warp = tid >> 5, lane = tid & 31;
    int v = blockIdx.x * 8 + warp;
    const float* w = wte + (size_t)v * Dq;
    float wv[8];
    float s = 0.f, ss = 0.f;
#pragma unroll
    for (int i = 0; i < 8; i++) {
        wv[i] = w[lane + i * 32];
        s += wv[i];
        ss += wv[i] * wv[i];
    }
#pragma unroll
    for (int o = 16; o; o >>= 1) {
        s += __shfl_xor_sync(0xffffffffu, s, o);
        ss += __shfl_xor_sync(0xffffffffu, ss, o);
    }
    float mean = s * (1.0f / Dq);
    float var = ss * (1.0f / Dq) - mean * mean;
    float rstd = rsqrtf(var + 1e-5f);
    float wn[8];
#pragma unroll
    for (int i = 0; i < 8; i++) wn[i] = (wv[i] - mean) * rstd * gs[lane + i * 32];
#pragma unroll
    for (int b = 0; b < Bq; b++) {
        float dot = 0.f;
#pragma unroll
        for (int i = 0; i < 8; i++) dot += wn[i] * xs[b * Dq + lane + i * 32];
#pragma unroll
        for (int o = 16; o; o >>= 1) dot += __shfl_xor_sync(0xffffffffu, dot, o);
        if (lane == 0) out[(size_t)b * Vq + v] = dot;
    }
}

// ---------------- launch ----------------
extern "C" void kernel_launch(void* const* d_in, const int* in_sizes, int n_in,
                              void* d_out, int out_size) {
    const int* tokens = (const int*)d_in[0];
    const float* wte = (const float*)d_in[1];
    const float* wpe = (const float*)d_in[2];
    const float* g_e = (const float*)d_in[3];
    const float* g_p = (const float*)d_in[4];
    const float* g_out = (const float*)d_in[5];
    const float* ff_w1 = (const float*)d_in[6];
    const float* ff_w2 = (const float*)d_in[7];
    const float* Wq = (const float*)d_in[8];
    const float* Wk = (const float*)d_in[9];
    const float* Wv = (const float*)d_in[10];
    float* out = (float*)d_out;

    constexpr int SM0 = 3 * (128 + 64) * 72 * 2;  // 82944 B
    constexpr int SM1 = 3 * (64 + 64) * 72 * 2;   // 55296 B
    cudaFuncSetAttribute(ffn_mma_kernel<128, 64, 0>,
                         cudaFuncAttributeMaxDynamicSharedMemorySize, SM0);
    cudaFuncSetAttribute(ffn_mma_kernel<64, 32, 1>,
                         cudaFuncAttributeMaxDynamicSharedMemorySize, SM1);

    // weight transposes (one launch)
    transpose_both_kernel<<<512, dim3(32, 8)>>>(ff_w1, ff_w2);
    // 1. embeddings + positional LN (+ fused bf16 p_raw)
    embed_ln_kernel<<<(Bq * Sq + Sq) / 8, 256>>>(tokens, wte, wpe, g_e, g_p);
    // 2/3. FFN on tensor cores
    ffn_mma_kernel<128, 64, 0><<<dim3(Hq / 64, Sq / 128), 128, SM0>>>();
    ffn_mma_kernel<64, 32, 1><<<dim3(Dq / 64, Sq / 64), 128, SM1>>>();
    // 4. per-layer score direction m_l
    qk_q_kernel<<<dim3(Lq, 8), 256>>>(Wq);
    qk_m_kernel<<<dim3(Lq, 32), 256>>>(Wk);
    // 5. scores -> exp (all 6 layers, one pass over p)
    score_kernel<<<Sq / 8, 256>>>();
    // 6. ctx partials + chunk sums
    ctx_kernel<<<dim3(32, Bq), 256>>>();
    // 7. Wv projection (+ reduce + softmax normalize)
    vproj_kernel<<<dim3(Lq, Bq), 256>>>(Wv);
    // 8. final LN
    final_ln_kernel<<<Bq, 256>>>(g_out);
    // 9. logits
    logits_kernel<<<Vq / 8, 256>>>(wte, g_e, out);
}

// round 8
// speedup vs baseline: 2.7127x; 1.0006x over previous
#include <cuda_runtime.h>
#include <cuda_bf16.h>
#include <math.h>
#include <stdint.h>

#define Bq 4
#define Sq 4096
#define Dq 256
#define Lq 6
#define Vq 32000
#define Hq 1024

// ---------------- scratch (no allocations allowed) ----------------
__device__ float g_ebuf[(size_t)Bq * Sq * Dq];   // e = ln(wte[tokens])        16MB
__device__ float g_p0buf[Sq * Dq];               // p_raw = ln(wpe[:S])         4MB
__device__ __nv_bfloat16 g_pA[Sq * Dq];          // bf16(p_raw)                 2MB
__device__ __nv_bfloat16 g_hbf[(size_t)Sq * Hq]; // bf16 FFN hidden             8MB
__device__ __nv_bfloat16 g_w1t[Hq * Dq];         // ff_w1^T  [H][D] bf16
__device__ float g_plast_part[8 * Dq];           // partials of h[S-1] @ ff_w2
__device__ float g_qpart[Lq * 8 * Dq];
__device__ float g_mbuf[Lq * Dq];
__device__ float g_w2m[Lq * Hq];                 // w2m_l = ff_w2 @ m_l
__device__ float g_abuf[Lq * Sq];                // exp(scores), unnormalized
__device__ float g_asum[32 * Lq];                // per-chunk sum of exp
__device__ float g_ctxpart[32 * Lq * Bq * Dq];
__device__ float g_attnout[Lq * Bq * Dq];
__device__ float g_xhat[Bq * Dq];

// ---------------- helpers ----------------
__device__ __forceinline__ uint32_t smem_u32(const void* p) {
    uint32_t a;
    asm("{ .reg .u64 t; cvta.to.shared.u64 t, %1; cvt.u32.u64 %0, t; }" : "=r"(a) : "l"(p));
    return a;
}

__device__ __forceinline__ void ldsm_x4(uint32_t* r, uint32_t addr) {
    asm volatile("ldmatrix.sync.aligned.m8n8.x4.shared.b16 {%0,%1,%2,%3}, [%4];"
                 : "=r"(r[0]), "=r"(r[1]), "=r"(r[2]), "=r"(r[3]) : "r"(addr));
}

__device__ __forceinline__ void mma_bf16(float* c, const uint32_t* a, const uint32_t* b) {
    asm volatile(
        "mma.sync.aligned.m16n8k16.row.col.f32.bf16.bf16.f32 "
        "{%0,%1,%2,%3}, {%4,%5,%6,%7}, {%8,%9}, {%0,%1,%2,%3};"
        : "+f"(c[0]), "+f"(c[1]), "+f"(c[2]), "+f"(c[3])
        : "r"(a[0]), "r"(a[1]), "r"(a[2]), "r"(a[3]), "r"(b[0]), "r"(b[1]));
}

__device__ __forceinline__ void cp_async16(uint32_t saddr, const void* gptr) {
    asm volatile("cp.async.cg.shared.global [%0], [%1], 16;" :: "r"(saddr), "l"(gptr));
}
#define CP_COMMIT() asm volatile("cp.async.commit_group;")
template <int N>
__device__ __forceinline__ void cp_wait() {
    asm volatile("cp.async.wait_group %0;" :: "n"(N));
}

__device__ __forceinline__ float2 blockReduceSum2_256(float a, float b) {
    __shared__ float sa[8], sb[8];
    int lane = threadIdx.x & 31, w = threadIdx.x >> 5;
#pragma unroll
    for (int o = 16; o; o >>= 1) {
        a += __shfl_xor_sync(0xffffffffu, a, o);
        b += __shfl_xor_sync(0xffffffffu, b, o);
    }
    if (lane == 0) { sa[w] = a; sb[w] = b; }
    __syncthreads();
    if (w == 0) {
        a = (lane < 8) ? sa[lane] : 0.f;
        b = (lane < 8) ? sb[lane] : 0.f;
#pragma unroll
        for (int o = 4; o; o >>= 1) {
            a += __shfl_xor_sync(0xffffffffu, a, o);
            b += __shfl_xor_sync(0xffffffffu, b, o);
        }
        if (lane == 0) { sa[0] = a; sb[0] = b; }
    }
    __syncthreads();
    float ra = sa[0], rb = sb[0];
    __syncthreads();
    return make_float2(ra, rb);
}

// ---------------- K1: embedding + positional LN (warp per row) ----------
__global__ void __launch_bounds__(256) embed_ln_kernel(
    const int* __restrict__ tokens, const float* __restrict__ wte,
    const float* __restrict__ wpe, const float* __restrict__ gew,
    const float* __restrict__ gpw) {
    int warp = threadIdx.x >> 5, lane = threadIdx.x & 31;
    int row = blockIdx.x * 8 + warp;
    const float* src;
    float* dst;
    const float* g;
    __nv_bfloat16* dst16 = nullptr;
    if (row < Bq * Sq) {
        int tok = __ldg(tokens + row);
        src = wte + (size_t)tok * Dq;
        dst = g_ebuf + (size_t)row * Dq;
        g = gew;
    } else {
        int s = row - Bq * Sq;
        src = wpe + (size_t)s * Dq;
        dst = g_p0buf + (size_t)s * Dq;
        dst16 = g_pA + (size_t)s * Dq;
        g = gpw;
    }
    float4 v0 = *(const float4*)(src + lane * 8);
    float4 v1 = *(const float4*)(src + lane * 8 + 4);
    float s1 = v0.x + v0.y + v0.z + v0.w + v1.x + v1.y + v1.z + v1.w;
    float s2 = v0.x * v0.x + v0.y * v0.y + v0.z * v0.z + v0.w * v0.w +
               v1.x * v1.x + v1.y * v1.y + v1.z * v1.z + v1.w * v1.w;
#pragma unroll
    for (int o = 16; o; o >>= 1) {
        s1 += __shfl_xor_sync(0xffffffffu, s1, o);
        s2 += __shfl_xor_sync(0xffffffffu, s2, o);
    }
    float mean = s1 * (1.0f / Dq);
    float var = s2 * (1.0f / Dq) - mean * mean;
    float rstd = rsqrtf(var + 1e-5f);
    float4 g0 = *(const float4*)(g + lane * 8);
    float4 g1 = *(const float4*)(g + lane * 8 + 4);
    float4 o0, o1;
    o0.x = (v0.x - mean) * rstd * g0.x;
    o0.y = (v0.y - mean) * rstd * g0.y;
    o0.z = (v0.z - mean) * rstd * g0.z;
    o0.w = (v0.w - mean) * rstd * g0.w;
    o1.x = (v1.x - mean) * rstd * g1.x;
    o1.y = (v1.y - mean) * rstd * g1.y;
    o1.z = (v1.z - mean) * rstd * g1.z;
    o1.w = (v1.w - mean) * rstd * g1.w;
    *(float4*)(dst + lane * 8) = o0;
    *(float4*)(dst + lane * 8 + 4) = o1;
    if (dst16) {
        __nv_bfloat162 b0 = __floats2bfloat162_rn(o0.x, o0.y);
        __nv_bfloat162 b1 = __floats2bfloat162_rn(o0.z, o0.w);
        __nv_bfloat162 b2 = __floats2bfloat162_rn(o1.x, o1.y);
        __nv_bfloat162 b3 = __floats2bfloat162_rn(o1.z, o1.w);
        uint4 u;
        u.x = reinterpret_cast<uint32_t&>(b0);
        u.y = reinterpret_cast<uint32_t&>(b1);
        u.z = reinterpret_cast<uint32_t&>(b2);
        u.w = reinterpret_cast<uint32_t&>(b3);
        *(uint4*)(dst16 + lane * 8) = u;
    }
}

// ---------------- prep: transpose ff_w1 [D][H] -> bf16 [H][D] ------------
__global__ void transpose_w1_kernel(const float* __restrict__ w1) {
    __shared__ float t[32][33];
    int bid = blockIdx.x;
    int c0 = (bid & 31) * 32, r0 = (bid >> 5) * 32;  // C=Hq, R=Dq
    int x = threadIdx.x, y = threadIdx.y;
#pragma unroll
    for (int i = 0; i < 32; i += 8) t[y + i][x] = w1[(size_t)(r0 + y + i) * Hq + c0 + x];
    __syncthreads();
#pragma unroll
    for (int i = 0; i < 32; i += 8)
        g_w1t[(size_t)(c0 + y + i) * Dq + r0 + x] = __float2bfloat16(t[x][y + i]);
}

// ---------------- FFN GEMM1: h = gelu(p_raw @ ff_w1) ----------------------
// BM=128, BN=64, BK=64; 4 warps (2x2), warp tile 64x32; grid (16, 32)
__global__ void __launch_bounds__(128) ffn_mma_kernel() {
    constexpr int BM = 128, BN = 64, BK = 64, LDS = 72, ST = 3;
    constexpr int Kd = Dq, Nd = Hq, NCH = Kd / BK;
    constexpr int wtM = 64, wtN = 32, MT = 4, NT = 2;

    extern __shared__ __nv_bfloat16 dynsm[];
    __nv_bfloat16* AsBase = dynsm;
    __nv_bfloat16* BsBase = dynsm + ST * BM * LDS;

    int tid = threadIdx.x, wid = tid >> 5, lane = tid & 31;
    int warp_m = wid & 1, warp_n = wid >> 1;
    int m0 = blockIdx.y * BM, n0 = blockIdx.x * BN;

    int a_row = warp_m * wtM + ((lane >> 3) & 1) * 8 + (lane & 7);
    int a_col = (lane >> 4) * 8;
    int b_row = warp_n * wtN + ((lane >> 4) & 1) * 8 + (lane & 7);
    int b_col = ((lane >> 3) & 1) * 8;

    auto load_stage = [&](int st, int k0) {
        __nv_bfloat16* As = AsBase + st * BM * LDS;
        __nv_bfloat16* Bs = BsBase + st * BN * LDS;
#pragma unroll
        for (int i = 0; i < 8; i++) {
            int id = tid + i * 128;
            int r = id >> 3, cc = (id & 7) * 8;
            cp_async16(smem_u32(As + r * LDS + cc), g_pA + (size_t)(m0 + r) * Kd + k0 + cc);
        }
#pragma unroll
        for (int i = 0; i < 4; i++) {
            int id = tid + i * 128;
            int r = id >> 3, cc = (id & 7) * 8;
            cp_async16(smem_u32(Bs + r * LDS + cc), g_w1t + (size_t)(n0 + r) * Kd + k0 + cc);
        }
        CP_COMMIT();
    };

    float c[MT][NT * 2][4] = {};

    load_stage(0, 0);
    load_stage(1, BK);
    for (int ch = 0; ch < NCH; ch++) {
        if (ch == NCH - 1) cp_wait<0>(); else cp_wait<1>();
        __syncthreads();
        if (ch + 2 < NCH) load_stage((ch + 2) % ST, (ch + 2) * BK);
        int st = ch % ST;
        uint32_t As_base = smem_u32(AsBase + st * BM * LDS);
        uint32_t Bs_base = smem_u32(BsBase + st * BN * LDS);
#pragma unroll
        for (int kk = 0; kk < BK / 16; kk++) {
            uint32_t a[MT][4], b[NT][4];
#pragma unroll
            for (int mt = 0; mt < MT; mt++)
                ldsm_x4(a[mt], As_base + ((a_row + mt * 16) * LDS + kk * 16 + a_col) * 2);
#pragma unroll
            for (int nt = 0; nt < NT; nt++)
                ldsm_x4(b[nt], Bs_base + ((b_row + nt * 16) * LDS + kk * 16 + b_col) * 2);
#pragma unroll
            for (int mt = 0; mt < MT; mt++)
#pragma unroll
                for (int nt = 0; nt < NT; nt++) {
                    mma_bf16(c[mt][nt * 2 + 0], a[mt], &b[nt][0]);
                    mma_bf16(c[mt][nt * 2 + 1], a[mt], &b[nt][2]);
                }
        }
    }

    int group = lane >> 2, tg = lane & 3;
#pragma unroll
    for (int mt = 0; mt < MT; mt++) {
#pragma unroll
        for (int nt = 0; nt < NT * 2; nt++) {
#pragma unroll
            for (int half = 0; half < 2; half++) {
                int m = m0 + warp_m * wtM + mt * 16 + group + half * 8;
                int n = n0 + warp_n * wtN + nt * 8 + tg * 2;
                float v0 = c[mt][nt][half * 2 + 0];
                float v1 = c[mt][nt][half * 2 + 1];
                v0 = 0.5f * v0 * (1.0f + erff(v0 * 0.70710678118654752f));
                v1 = 0.5f * v1 * (1.0f + erff(v1 * 0.70710678118654752f));
                __nv_bfloat162 h = __floats2bfloat162_rn(v0, v1);
                *(uint32_t*)&g_hbf[(size_t)m * Nd + n] = reinterpret_cast<uint32_t&>(h);
            }
        }
    }
}

// ---------------- K3: p_last partials = h[S-1] @ ff_w2 -------------------
__global__ void plast_kernel(const float* __restrict__ ff_w2) {
    int cc = blockIdx.x;  // 8 chunks of 128 k
    int j = threadIdx.x;
    __shared__ float hsm[128];
    if (j < 128) hsm[j] = __bfloat162float(g_hbf[(size_t)(Sq - 1) * Hq + cc * 128 + j]);
    __syncthreads();
    float a = 0.f;
#pragma unroll 8
    for (int k = 0; k < 128; k++)
        a += hsm[k] * ff_w2[(size_t)(cc * 128 + k) * Dq + j];
    g_plast_part[cc * Dq + j] = a;
}

// ---------------- K4a: partial q = Wq^T p_last ----------------
__global__ void qk_q_kernel(const float* __restrict__ Wq) {
    int l = blockIdx.x, c = blockIdx.y;
    int j = threadIdx.x;
    __shared__ float pl[32];
    if (j < 32) {
        float v = g_p0buf[(size_t)(Sq - 1) * Dq + c * 32 + j];
#pragma unroll
        for (int cc = 0; cc < 8; cc++) v += g_plast_part[cc * Dq + c * 32 + j];
        pl[j] = v;
    }
    __syncthreads();
    const float* wq = Wq + (size_t)l * Dq * Dq + (size_t)c * 32 * Dq;
    float acc = 0.f;
#pragma unroll
    for (int i = 0; i < 32; i++) acc += pl[i] * wq[(size_t)i * Dq + j];
    g_qpart[(l * 8 + c) * Dq + j] = acc;
}

// ---------------- K4b: m_l = Wk_l @ q_l ----------------
__global__ void qk_m_kernel(const float* __restrict__ Wk) {
    int l = blockIdx.x;
    int tid = threadIdx.x;
    int warp = tid >> 5, lane = tid & 31;
    __shared__ float qs[Dq];
    {
        float acc = 0.f;
#pragma unroll
        for (int c = 0; c < 8; c++) acc += g_qpart[(l * 8 + c) * Dq + tid];
        qs[tid] = acc;
    }
    __syncthreads();
    int j = blockIdx.y * 8 + warp;
    const float* wk = Wk + (size_t)l * Dq * Dq + (size_t)j * Dq;
    float m = 0.f;
#pragma unroll
    for (int i = 0; i < 8; i++) {
        int idx = lane + i * 32;
        m += wk[idx] * qs[idx];
    }
#pragma unroll
    for (int o = 16; o; o >>= 1) m += __shfl_xor_sync(0xffffffffu, m, o);
    if (lane == 0) g_mbuf[l * Dq + j] = m;
}

// ---------------- K5: w2m_l = ff_w2 @ m_l (warp per row) -----------------
__global__ void w2m_kernel(const float* __restrict__ ff_w2) {
    int l = blockIdx.y;
    int tid = threadIdx.x;
    __shared__ float msm[Dq];
    msm[tid] = g_mbuf[l * Dq + tid];
    __syncthreads();
    int warp = tid >> 5, lane = tid & 31;
    int k = blockIdx.x * 8 + warp;  // k < Hq
    const float* row = ff_w2 + (size_t)k * Dq;
    float a = 0.f;
#pragma unroll
    for (int i = 0; i < 8; i++) {
        int idx = lane + i * 32;
        a += row[idx] * msm[idx];
    }
#pragma unroll
    for (int o = 16; o; o >>= 1) a += __shfl_xor_sync(0xffffffffu, a, o);
    if (lane == 0) g_w2m[l * Hq + k] = a;
}

// ---------------- K6: scores -> exp (GEMM2 folded in) --------------------
// s[l][t] = (p0[t].m_l + h[t].w2m_l) / 16 ; write exp (O(1) scores, safe)
__global__ void __launch_bounds__(256) score_kernel() {
    __shared__ float m_sm[Lq * Dq];    // 6KB
    __shared__ float w_sm[Lq * Hq];    // 24KB
    int tid = threadIdx.x;
    for (int i = tid; i < Lq * Dq; i += 256) m_sm[i] = g_mbuf[i];
    for (int i = tid; i < Lq * Hq; i += 256) w_sm[i] = g_w2m[i];
    __syncthreads();
    int warp = tid >> 5, lane = tid & 31;
    int t = blockIdx.x * 8 + warp;
    const float* p = g_p0buf + (size_t)t * Dq;
    float pv[8];
#pragma unroll
    for (int i = 0; i < 8; i++) pv[i] = p[lane + i * 32];
    const __nv_bfloat162* h2 = (const __nv_bfloat162*)(g_hbf + (size_t)t * Hq);
    float hx[16], hy[16];
#pragma unroll
    for (int i = 0; i < 16; i++) {
        __nv_bfloat162 v = h2[lane + i * 32];
        hx[i] = __bfloat162float(v.x);
        hy[i] = __bfloat162float(v.y);
    }
    float acc[Lq];
#pragma unroll
    for (int l = 0; l < Lq; l++) {
        float a = 0.f;
        const float* mrow = m_sm + l * Dq;
#pragma unroll
        for (int i = 0; i < 8; i++) a += pv[i] * mrow[lane + i * 32];
        const float* wrow = w_sm + l * Hq;
#pragma unroll
        for (int i = 0; i < 16; i++) {
            float2 w2 = *(const float2*)&wrow[2 * (lane + i * 32)];
            a += hx[i] * w2.x + hy[i] * w2.y;
        }
        acc[l] = a;
    }
#pragma unroll
    for (int l = 0; l < Lq; l++) {
#pragma unroll
        for (int o = 16; o; o >>= 1) acc[l] += __shfl_xor_sync(0xffffffffu, acc[l], o);
    }
    if (lane == 0) {
#pragma unroll
        for (int l = 0; l < Lq; l++) g_abuf[l * Sq + t] = expf(acc[l] * 0.0625f);
    }
}

// ---------------- K7: ctx partials + per-chunk exp sums ------------------
__global__ void ctx_kernel() {
    int chunk = blockIdx.x;
    int b = blockIdx.y;
    int d = threadIdx.x;
    __shared__ float as_[Lq][128];
    for (int i = d; i < Lq * 128; i += 256) {
        int l = i >> 7, t = i & 127;
        as_[l][t] = g_abuf[l * Sq + chunk * 128 + t];
    }
    __syncthreads();
    float acc[Lq] = {};
    const float* ep = g_ebuf + ((size_t)b * Sq + (size_t)chunk * 128) * Dq + d;
#pragma unroll 4
    for (int t = 0; t < 128; t++) {
        float ev = ep[(size_t)t * Dq];
#pragma unroll
        for (int l = 0; l < Lq; l++) acc[l] += as_[l][t] * ev;
    }
#pragma unroll
    for (int l = 0; l < Lq; l++)
        g_ctxpart[(((size_t)chunk * Lq + l) * Bq + b) * Dq + d] = acc[l];
    if (b == 0 && d < Lq) {
        float s = 0.f;
#pragma unroll 8
        for (int t = 0; t < 128; t++) s += as_[d][t];
        g_asum[chunk * Lq + d] = s;
    }
}

// ---------------- K8: Wv projection (fused reduce + normalize) -----------
__global__ void vproj_kernel(const float* __restrict__ Wv) {
    int l = blockIdx.x, b = blockIdx.y, d = threadIdx.x;
    __shared__ float c[Dq];
    float acc = 0.f;
#pragma unroll
    for (int ch = 0; ch < 32; ch++)
        acc += g_ctxpart[(((size_t)ch * Lq + l) * Bq + b) * Dq + d];
    float ssum = 0.f;
#pragma unroll
    for (int ch = 0; ch < 32; ch++) ssum += g_asum[ch * Lq + l];
    c[d] = acc * (1.0f / ssum);
    __syncthreads();
    const float* wv = Wv + (size_t)l * Dq * Dq;
    float o = 0.f;
#pragma unroll 4
    for (int k = 0; k < Dq; k++) o += c[k] * wv[(size_t)k * Dq + d];
    g_attnout[((size_t)l * Bq + b) * Dq + d] = o;
}

// ---------------- K9: final LN ----------------
__global__ void final_ln_kernel(const float* __restrict__ g_out_w) {
    int b = blockIdx.x, d = threadIdx.x;
    float x = g_ebuf[((size_t)b * Sq + Sq - 1) * Dq + d] + g_p0buf[(size_t)(Sq - 1) * Dq + d];
#pragma unroll
    for (int l = 0; l < Lq; l++) x += g_attnout[((size_t)l * Bq + b) * Dq + d];
    float2 r = blockReduceSum2_256(x, x * x);
    float mean = r.x * (1.0f / Dq);
    float var = r.y * (1.0f / Dq) - mean * mean;
    g_xhat[b * Dq + d] = (x - mean) * rsqrtf(var + 1e-5f) * g_out_w[d];
}

// ---------------- K10: logits ----------------
__global__ void logits_kernel(const float* __restrict__ wte,
                              const float* __restrict__ gew,
                              float* __restrict__ out) {
    __shared__ float xs[Bq * Dq];
    __shared__ float gs[Dq];
    int tid = threadIdx.x;
    for (int i = tid; i < Bq * Dq; i += 256) xs[i] = g_xhat[i];
    gs[tid] = gew[tid];
    __syncthreads();
    int warp = tid >> 5, lane = tid & 31;
    int v = blockIdx.x * 8 + warp;
    const float* w = wte + (size_t)v * Dq;
    float wv[8];
    float s = 0.f, ss = 0.f;
#pragma unroll
    for (int i = 0; i < 8; i++) {
        wv[i] = w[lane + i * 32];
        s += wv[i];
        ss += wv[i] * wv[i];
    }
#pragma unroll
    for (int o = 16; o; o >>= 1) {
        s += __shfl_xor_sync(0xffffffffu, s, o);
        ss += __shfl_xor_sync(0xffffffffu, ss, o);
    }
    float mean = s * (1.0f / Dq);
    float var = ss * (1.0f / Dq) - mean * mean;
    float rstd = rsqrtf(var + 1e-5f);
    float wn[8];
#pragma unroll
    for (int i = 0; i < 8; i++) wn[i] = (wv[i] - mean) * rstd * gs[lane + i * 32];
#pragma unroll
    for (int b = 0; b < Bq; b++) {
        float dot = 0.f;
#pragma unroll
        for (int i = 0; i < 8; i++) dot += wn[i] * xs[b * Dq + lane + i * 32];
#pragma unroll
        for (int o = 16; o; o >>= 1) dot += __shfl_xor_sync(0xffffffffu, dot, o);
        if (lane == 0) out[(size_t)b * Vq + v] = dot;
    }
}

// ---------------- launch ----------------
extern "C" void kernel_launch(void* const* d_in, const int* in_sizes, int n_in,
                              void* d_out, int out_size) {
    const int* tokens = (const int*)d_in[0];
    const float* wte = (const float*)d_in[1];
    const float* wpe = (const float*)d_in[2];
    const float* g_e = (const float*)d_in[3];
    const float* g_p = (const float*)d_in[4];
    const float* g_out = (const float*)d_in[5];
    const float* ff_w1 = (const float*)d_in[6];
    const float* ff_w2 = (const float*)d_in[7];
    const float* Wq = (const float*)d_in[8];
    const float* Wk = (const float*)d_in[9];
    const float* Wv = (const float*)d_in[10];
    float* out = (float*)d_out;

    constexpr int SM0 = 3 * (128 + 64) * 72 * 2;  // 82944 B
    cudaFuncSetAttribute(ffn_mma_kernel, cudaFuncAttributeMaxDynamicSharedMemorySize, SM0);

    // w1 transpose
    transpose_w1_kernel<<<256, dim3(32, 8)>>>(ff_w1);
    // 1. embeddings + positional LN (+ fused bf16 p_raw)
    embed_ln_kernel<<<(Bq * Sq + Sq) / 8, 256>>>(tokens, wte, wpe, g_e, g_p);
    // 2. FFN GEMM1 only: h = gelu(p0 @ W1)
    ffn_mma_kernel<<<dim3(Hq / 64, Sq / 128), 128, SM0>>>();
    // 3. p_last = p0[S-1] + h[S-1] @ W2 (partials)
    plast_kernel<<<8, 256>>>(ff_w2);
    // 4. per-layer score direction m_l
    qk_q_kernel<<<dim3(Lq, 8), 256>>>(Wq);
    qk_m_kernel<<<dim3(Lq, 32), 256>>>(Wk);
    // 5. w2m_l = W2 @ m_l
    w2m_kernel<<<dim3(Hq / 8, Lq), 256>>>(ff_w2);
    // 6. scores -> exp (GEMM2 folded in via h . w2m)
    score_kernel<<<Sq / 8, 256>>>();
    // 7. ctx partials + chunk sums
    ctx_kernel<<<dim3(32, Bq), 256>>>();
    // 8. Wv projection (+ reduce + normalize)
    vproj_kernel<<<dim3(Lq, Bq), 256>>>(Wv);
    // 9. final LN
    final_ln_kernel<<<Bq, 256>>>(g_out);
    // 10. logits
    logits_kernel<<<Vq / 8, 256>>>(wte, g_e, out);
}

// round 9
// speedup vs baseline: 2.7637x; 1.0188x over previous
#include <cuda_runtime.h>
#include <cuda_bf16.h>
#include <math.h>
#include <stdint.h>

#define Bq 4
#define Sq 4096
#define Dq 256
#define Lq 6
#define Vq 32000
#define Hq 1024

// ---------------- scratch (no allocations allowed) ----------------
__device__ float g_ebuf[(size_t)Bq * Sq * Dq];   // e = ln(wte[tokens])        16MB
__device__ float g_p0buf[Sq * Dq];               // p_raw = ln(wpe[:S])         4MB
__device__ __nv_bfloat16 g_pA[Sq * Dq];          // bf16(p_raw)                 2MB
__device__ __nv_bfloat16 g_hbf[(size_t)Sq * Hq]; // bf16 FFN hidden             8MB
__device__ __nv_bfloat16 g_w1t[Hq * Dq];         // ff_w1^T  [H][D] bf16
__device__ float g_plast_part[64 * Dq];          // partials of h[S-1] @ ff_w2
__device__ float g_qpart[Lq * 8 * Dq];
__device__ float g_mbuf[Lq * Dq];
__device__ float g_w2m[Lq * Hq];                 // w2m_l = ff_w2 @ m_l
__device__ float g_abuf[Lq * Sq];                // exp(scores), unnormalized
__device__ float g_asum[32 * Lq];                // per-chunk sum of exp
__device__ float g_ctxpart[32 * Lq * Bq * Dq];
__device__ float g_attnout[Lq * Bq * Dq];
__device__ float g_xhat[Bq * Dq];

// ---------------- helpers ----------------
__device__ __forceinline__ uint32_t smem_u32(const void* p) {
    uint32_t a;
    asm("{ .reg .u64 t; cvta.to.shared.u64 t, %1; cvt.u32.u64 %0, t; }" : "=r"(a) : "l"(p));
    return a;
}

__device__ __forceinline__ void ldsm_x4(uint32_t* r, uint32_t addr) {
    asm volatile("ldmatrix.sync.aligned.m8n8.x4.shared.b16 {%0,%1,%2,%3}, [%4];"
                 : "=r"(r[0]), "=r"(r[1]), "=r"(r[2]), "=r"(r[3]) : "r"(addr));
}

__device__ __forceinline__ void mma_bf16(float* c, const uint32_t* a, const uint32_t* b) {
    asm volatile(
        "mma.sync.aligned.m16n8k16.row.col.f32.bf16.bf16.f32 "
        "{%0,%1,%2,%3}, {%4,%5,%6,%7}, {%8,%9}, {%0,%1,%2,%3};"
        : "+f"(c[0]), "+f"(c[1]), "+f"(c[2]), "+f"(c[3])
        : "r"(a[0]), "r"(a[1]), "r"(a[2]), "r"(a[3]), "r"(b[0]), "r"(b[1]));
}

__device__ __forceinline__ void cp_async16(uint32_t saddr, const void* gptr) {
    asm volatile("cp.async.cg.shared.global [%0], [%1], 16;" :: "r"(saddr), "l"(gptr));
}
#define CP_COMMIT() asm volatile("cp.async.commit_group;")
template <int N>
__device__ __forceinline__ void cp_wait() {
    asm volatile("cp.async.wait_group %0;" :: "n"(N));
}

__device__ __forceinline__ float2 blockReduceSum2_256(float a, float b) {
    __shared__ float sa[8], sb[8];
    int lane = threadIdx.x & 31, w = threadIdx.x >> 5;
#pragma unroll
    for (int o = 16; o; o >>= 1) {
        a += __shfl_xor_sync(0xffffffffu, a, o);
        b += __shfl_xor_sync(0xffffffffu, b, o);
    }
    if (lane == 0) { sa[w] = a; sb[w] = b; }
    __syncthreads();
    if (w == 0) {
        a = (lane < 8) ? sa[lane] : 0.f;
        b = (lane < 8) ? sb[lane] : 0.f;
#pragma unroll
        for (int o = 4; o; o >>= 1) {
            a += __shfl_xor_sync(0xffffffffu, a, o);
            b += __shfl_xor_sync(0xffffffffu, b, o);
        }
        if (lane == 0) { sa[0] = a; sb[0] = b; }
    }
    __syncthreads();
    float ra = sa[0], rb = sb[0];
    __syncthreads();
    return make_float2(ra, rb);
}

// ---------------- K1: embedding + positional LN (warp per row) ----------
__global__ void __launch_bounds__(256) embed_ln_kernel(
    const int* __restrict__ tokens, const float* __restrict__ wte,
    const float* __restrict__ wpe, const float* __restrict__ gew,
    const float* __restrict__ gpw) {
    int warp = threadIdx.x >> 5, lane = threadIdx.x & 31;
    int row = blockIdx.x * 8 + warp;
    const float* src;
    float* dst;
    const float* g;
    __nv_bfloat16* dst16 = nullptr;
    if (row < Bq * Sq) {
        int tok = __ldg(tokens + row);
        src = wte + (size_t)tok * Dq;
        dst = g_ebuf + (size_t)row * Dq;
        g = gew;
    } else {
        int s = row - Bq * Sq;
        src = wpe + (size_t)s * Dq;
        dst = g_p0buf + (size_t)s * Dq;
        dst16 = g_pA + (size_t)s * Dq;
        g = gpw;
    }
    float4 v0 = *(const float4*)(src + lane * 8);
    float4 v1 = *(const float4*)(src + lane * 8 + 4);
    float s1 = v0.x + v0.y + v0.z + v0.w + v1.x + v1.y + v1.z + v1.w;
    float s2 = v0.x * v0.x + v0.y * v0.y + v0.z * v0.z + v0.w * v0.w +
               v1.x * v1.x + v1.y * v1.y + v1.z * v1.z + v1.w * v1.w;
#pragma unroll
    for (int o = 16; o; o >>= 1) {
        s1 += __shfl_xor_sync(0xffffffffu, s1, o);
        s2 += __shfl_xor_sync(0xffffffffu, s2, o);
    }
    float mean = s1 * (1.0f / Dq);
    float var = s2 * (1.0f / Dq) - mean * mean;
    float rstd = rsqrtf(var + 1e-5f);
    float4 g0 = *(const float4*)(g + lane * 8);
    float4 g1 = *(const float4*)(g + lane * 8 + 4);
    float4 o0, o1;
    o0.x = (v0.x - mean) * rstd * g0.x;
    o0.y = (v0.y - mean) * rstd * g0.y;
    o0.z = (v0.z - mean) * rstd * g0.z;
    o0.w = (v0.w - mean) * rstd * g0.w;
    o1.x = (v1.x - mean) * rstd * g1.x;
    o1.y = (v1.y - mean) * rstd * g1.y;
    o1.z = (v1.z - mean) * rstd * g1.z;
    o1.w = (v1.w - mean) * rstd * g1.w;
    *(float4*)(dst + lane * 8) = o0;
    *(float4*)(dst + lane * 8 + 4) = o1;
    if (dst16) {
        __nv_bfloat162 b0 = __floats2bfloat162_rn(o0.x, o0.y);
        __nv_bfloat162 b1 = __floats2bfloat162_rn(o0.z, o0.w);
        __nv_bfloat162 b2 = __floats2bfloat162_rn(o1.x, o1.y);
        __nv_bfloat162 b3 = __floats2bfloat162_rn(o1.z, o1.w);
        uint4 u;
        u.x = reinterpret_cast<uint32_t&>(b0);
        u.y = reinterpret_cast<uint32_t&>(b1);
        u.z = reinterpret_cast<uint32_t&>(b2);
        u.w = reinterpret_cast<uint32_t&>(b3);
        *(uint4*)(dst16 + lane * 8) = u;
    }
}

// ---------------- prep: transpose ff_w1 [D][H] -> bf16 [H][D] ------------
__global__ void transpose_w1_kernel(const float* __restrict__ w1) {
    __shared__ float t[32][33];
    int bid = blockIdx.x;
    int c0 = (bid & 31) * 32, r0 = (bid >> 5) * 32;  // C=Hq, R=Dq
    int x = threadIdx.x, y = threadIdx.y;
#pragma unroll
    for (int i = 0; i < 32; i += 8) t[y + i][x] = w1[(size_t)(r0 + y + i) * Hq + c0 + x];
    __syncthreads();
#pragma unroll
    for (int i = 0; i < 32; i += 8)
        g_w1t[(size_t)(c0 + y + i) * Dq + r0 + x] = __float2bfloat16(t[x][y + i]);
}

// ---------------- FFN GEMM1: h = gelu(p_raw @ ff_w1) ----------------------
// BM=128, BN=64, BK=64; 4 warps (2x2), warp tile 64x32; grid (16, 32)
__global__ void __launch_bounds__(128) ffn_mma_kernel() {
    constexpr int BM = 128, BN = 64, BK = 64, LDS = 72, ST = 3;
    constexpr int Kd = Dq, Nd = Hq, NCH = Kd / BK;
    constexpr int wtM = 64, wtN = 32, MT = 4, NT = 2;

    extern __shared__ __nv_bfloat16 dynsm[];
    __nv_bfloat16* AsBase = dynsm;
    __nv_bfloat16* BsBase = dynsm + ST * BM * LDS;

    int tid = threadIdx.x, wid = tid >> 5, lane = tid & 31;
    int warp_m = wid & 1, warp_n = wid >> 1;
    int m0 = blockIdx.y * BM, n0 = blockIdx.x * BN;

    int a_row = warp_m * wtM + ((lane >> 3) & 1) * 8 + (lane & 7);
    int a_col = (lane >> 4) * 8;
    int b_row = warp_n * wtN + ((lane >> 4) & 1) * 8 + (lane & 7);
    int b_col = ((lane >> 3) & 1) * 8;

    auto load_stage = [&](int st, int k0) {
        __nv_bfloat16* As = AsBase + st * BM * LDS;
        __nv_bfloat16* Bs = BsBase + st * BN * LDS;
#pragma unroll
        for (int i = 0; i < 8; i++) {
            int id = tid + i * 128;
            int r = id >> 3, cc = (id & 7) * 8;
            cp_async16(smem_u32(As + r * LDS + cc), g_pA + (size_t)(m0 + r) * Kd + k0 + cc);
        }
#pragma unroll
        for (int i = 0; i < 4; i++) {
            int id = tid + i * 128;
            int r = id >> 3, cc = (id & 7) * 8;
            cp_async16(smem_u32(Bs + r * LDS + cc), g_w1t + (size_t)(n0 + r) * Kd + k0 + cc);
        }
        CP_COMMIT();
    };

    float c[MT][NT * 2][4] = {};

    load_stage(0, 0);
    load_stage(1, BK);
    for (int ch = 0; ch < NCH; ch++) {
        if (ch == NCH - 1) cp_wait<0>(); else cp_wait<1>();
        __syncthreads();
        if (ch + 2 < NCH) load_stage((ch + 2) % ST, (ch + 2) * BK);
        int st = ch % ST;
        uint32_t As_base = smem_u32(AsBase + st * BM * LDS);
        uint32_t Bs_base = smem_u32(BsBase + st * BN * LDS);
#pragma unroll
        for (int kk = 0; kk < BK / 16; kk++) {
            uint32_t a[MT][4], b[NT][4];
#pragma unroll
            for (int mt = 0; mt < MT; mt++)
                ldsm_x4(a[mt], As_base + ((a_row + mt * 16) * LDS + kk * 16 + a_col) * 2);
#pragma unroll
            for (int nt = 0; nt < NT; nt++)
                ldsm_x4(b[nt], Bs_base + ((b_row + nt * 16) * LDS + kk * 16 + b_col) * 2);
#pragma unroll
            for (int mt = 0; mt < MT; mt++)
#pragma unroll
                for (int nt = 0; nt < NT; nt++) {
                    mma_bf16(c[mt][nt * 2 + 0], a[mt], &b[nt][0]);
                    mma_bf16(c[mt][nt * 2 + 1], a[mt], &b[nt][2]);
                }
        }
    }

    int group = lane >> 2, tg = lane & 3;
#pragma unroll
    for (int mt = 0; mt < MT; mt++) {
#pragma unroll
        for (int nt = 0; nt < NT * 2; nt++) {
#pragma unroll
            for (int half = 0; half < 2; half++) {
                int m = m0 + warp_m * wtM + mt * 16 + group + half * 8;
                int n = n0 + warp_n * wtN + nt * 8 + tg * 2;
                float v0 = c[mt][nt][half * 2 + 0];
                float v1 = c[mt][nt][half * 2 + 1];
                v0 = 0.5f * v0 * (1.0f + erff(v0 * 0.70710678118654752f));
                v1 = 0.5f * v1 * (1.0f + erff(v1 * 0.70710678118654752f));
                __nv_bfloat162 h = __floats2bfloat162_rn(v0, v1);
                *(uint32_t*)&g_hbf[(size_t)m * Nd + n] = reinterpret_cast<uint32_t&>(h);
            }
        }
    }
}

// ---------------- K3: p_last partials = h[S-1] @ ff_w2 (64-way split) ----
__global__ void plast_kernel(const float* __restrict__ ff_w2) {
    int cc = blockIdx.x;  // 64 chunks of 16 k
    int j = threadIdx.x;
    __shared__ float hsm[16];
    if (j < 16) hsm[j] = __bfloat162float(g_hbf[(size_t)(Sq - 1) * Hq + cc * 16 + j]);
    __syncthreads();
    const float* w = ff_w2 + (size_t)cc * 16 * Dq + j;
    float a = 0.f;
#pragma unroll
    for (int k = 0; k < 16; k++)
        a += hsm[k] * w[(size_t)k * Dq];
    g_plast_part[cc * Dq + j] = a;
}

// ---------------- K4a: partial q = Wq^T p_last ----------------
__global__ void qk_q_kernel(const float* __restrict__ Wq) {
    int l = blockIdx.x, c = blockIdx.y;
    int j = threadIdx.x;
    __shared__ float pl[32];
    if (j < 32) {
        float v = g_p0buf[(size_t)(Sq - 1) * Dq + c * 32 + j];
#pragma unroll
        for (int cc = 0; cc < 64; cc++) v += g_plast_part[cc * Dq + c * 32 + j];
        pl[j] = v;
    }
    __syncthreads();
    const float* wq = Wq + (size_t)l * Dq * Dq + (size_t)c * 32 * Dq;
    float acc = 0.f;
#pragma unroll
    for (int i = 0; i < 32; i++) acc += pl[i] * wq[(size_t)i * Dq + j];
    g_qpart[(l * 8 + c) * Dq + j] = acc;
}

// ---------------- K4b: m_l = Wk_l @ q_l ----------------
__global__ void qk_m_kernel(const float* __restrict__ Wk) {
    int l = blockIdx.x;
    int tid = threadIdx.x;
    int warp = tid >> 5, lane = tid & 31;
    __shared__ float qs[Dq];
    {
        float acc = 0.f;
#pragma unroll
        for (int c = 0; c < 8; c++) acc += g_qpart[(l * 8 + c) * Dq + tid];
        qs[tid] = acc;
    }
    __syncthreads();
    int j = blockIdx.y * 8 + warp;
    const float* wk = Wk + (size_t)l * Dq * Dq + (size_t)j * Dq;
    float m = 0.f;
#pragma unroll
    for (int i = 0; i < 8; i++) {
        int idx = lane + i * 32;
        m += wk[idx] * qs[idx];
    }
#pragma unroll
    for (int o = 16; o; o >>= 1) m += __shfl_xor_sync(0xffffffffu, m, o);
    if (lane == 0) g_mbuf[l * Dq + j] = m;
}

// ---------------- K5: w2m_l = ff_w2 @ m_l (warp per row) -----------------
__global__ void w2m_kernel(const float* __restrict__ ff_w2) {
    int l = blockIdx.y;
    int tid = threadIdx.x;
    __shared__ float msm[Dq];
    msm[tid] = g_mbuf[l * Dq + tid];
    __syncthreads();
    int warp = tid >> 5, lane = tid & 31;
    int k = blockIdx.x * 8 + warp;  // k < Hq
    const float* row = ff_w2 + (size_t)k * Dq;
    float a = 0.f;
#pragma unroll
    for (int i = 0; i < 8; i++) {
        int idx = lane + i * 32;
        a += row[idx] * msm[idx];
    }
#pragma unroll
    for (int o = 16; o; o >>= 1) a += __shfl_xor_sync(0xffffffffu, a, o);
    if (lane == 0) g_w2m[l * Hq + k] = a;
}

// ---------------- K6: scores -> exp (GEMM2 folded in) --------------------
__global__ void __launch_bounds__(256) score_kernel() {
    __shared__ float m_sm[Lq * Dq];    // 6KB
    __shared__ float w_sm[Lq * Hq];    // 24KB
    int tid = threadIdx.x;
    for (int i = tid; i < Lq * Dq; i += 256) m_sm[i] = g_mbuf[i];
    for (int i = tid; i < Lq * Hq; i += 256) w_sm[i] = g_w2m[i];
    __syncthreads();
    int warp = tid >> 5, lane = tid & 31;
    int t = blockIdx.x * 8 + warp;
    const float* p = g_p0buf + (size_t)t * Dq;
    float pv[8];
#pragma unroll
    for (int i = 0; i < 8; i++) pv[i] = p[lane + i * 32];
    const __nv_bfloat162* h2 = (const __nv_bfloat162*)(g_hbf + (size_t)t * Hq);
    float hx[16], hy[16];
#pragma unroll
    for (int i = 0; i < 16; i++) {
        __nv_bfloat162 v = h2[lane + i * 32];
        hx[i] = __bfloat162float(v.x);
        hy[i] = __bfloat162float(v.y);
    }
    float acc[Lq];
#pragma unroll
    for (int l = 0; l < Lq; l++) {
        float a = 0.f;
        const float* mrow = m_sm + l * Dq;
#pragma unroll
        for (int i = 0; i < 8; i++) a += pv[i] * mrow[lane + i * 32];
        const float* wrow = w_sm + l * Hq;
#pragma unroll
        for (int i = 0; i < 16; i++) {
            float2 w2 = *(const float2*)&wrow[2 * (lane + i * 32)];
            a += hx[i] * w2.x + hy[i] * w2.y;
        }
        acc[l] = a;
    }
#pragma unroll
    for (int l = 0; l < Lq; l++) {
#pragma unroll
        for (int o = 16; o; o >>= 1) acc[l] += __shfl_xor_sync(0xffffffffu, acc[l], o);
    }
    if (lane == 0) {
#pragma unroll
        for (int l = 0; l < Lq; l++) g_abuf[l * Sq + t] = expf(acc[l] * 0.0625f);
    }
}

// ---------------- K7: ctx partials + per-chunk exp sums ------------------
__global__ void ctx_kernel() {
    int chunk = blockIdx.x;
    int b = blockIdx.y;
    int d = threadIdx.x;
    __shared__ float as_[Lq][128];
    for (int i = d; i < Lq * 128; i += 256) {
        int l = i >> 7, t = i & 127;
        as_[l][t] = g_abuf[l * Sq + chunk * 128 + t];
    }
    __syncthreads();
    float acc[Lq] = {};
    const float* ep = g_ebuf + ((size_t)b * Sq + (size_t)chunk * 128) * Dq + d;
#pragma unroll 4
    for (int t = 0; t < 128; t++) {
        float ev = ep[(size_t)t * Dq];
#pragma unroll
        for (int l = 0; l < Lq; l++) acc[l] += as_[l][t] * ev;
    }
#pragma unroll
    for (int l = 0; l < Lq; l++)
        g_ctxpart[(((size_t)chunk * Lq + l) * Bq + b) * Dq + d] = acc[l];
    if (b == 0 && d < Lq) {
        float s = 0.f;
#pragma unroll 8
        for (int t = 0; t < 128; t++) s += as_[d][t];
        g_asum[chunk * Lq + d] = s;
    }
}

// ---------------- K8: Wv projection (fused reduce + normalize) -----------
__global__ void vproj_kernel(const float* __restrict__ Wv) {
    int l = blockIdx.x, b = blockIdx.y, d = threadIdx.x;
    __shared__ float c[Dq];
    float acc = 0.f;
#pragma unroll
    for (int ch = 0; ch < 32; ch++)
        acc += g_ctxpart[(((size_t)ch * Lq + l) * Bq + b) * Dq + d];
    float ssum = 0.f;
#pragma unroll
    for (int ch = 0; ch < 32; ch++) ssum += g_asum[ch * Lq + l];
    c[d] = acc * (1.0f / ssum);
    __syncthreads();
    const float* wv = Wv + (size_t)l * Dq * Dq;
    float o = 0.f;
#pragma unroll 4
    for (int k = 0; k < Dq; k++) o += c[k] * wv[(size_t)k * Dq + d];
    g_attnout[((size_t)l * Bq + b) * Dq + d] = o;
}

// ---------------- K9: final LN ----------------
__global__ void final_ln_kernel(const float* __restrict__ g_out_w) {
    int b = blockIdx.x, d = threadIdx.x;
    float x = g_ebuf[((size_t)b * Sq + Sq - 1) * Dq + d] + g_p0buf[(size_t)(Sq - 1) * Dq + d];
#pragma unroll
    for (int l = 0; l < Lq; l++) x += g_attnout[((size_t)l * Bq + b) * Dq + d];
    float2 r = blockReduceSum2_256(x, x * x);
    float mean = r.x * (1.0f / Dq);
    float var = r.y * (1.0f / Dq) - mean * mean;
    g_xhat[b * Dq + d] = (x - mean) * rsqrtf(var + 1e-5f) * g_out_w[d];
}

// ---------------- K10: logits ----------------
__global__ void logits_kernel(const float* __restrict__ wte,
                              const float* __restrict__ gew,
                              float* __restrict__ out) {
    __shared__ float xs[Bq * Dq];
    __shared__ float gs[Dq];
    int tid = threadIdx.x;
    for (int i = tid; i < Bq * Dq; i += 256) xs[i] = g_xhat[i];
    gs[tid] = gew[tid];
    __syncthreads();
    int warp = tid >> 5, lane = tid & 31;
    int v = blockIdx.x * 8 + warp;
    const float* w = wte + (size_t)v * Dq;
    float wv[8];
    float s = 0.f, ss = 0.f;
#pragma unroll
    for (int i = 0; i < 8; i++) {
        wv[i] = w[lane + i * 32];
        s += wv[i];
        ss += wv[i] * wv[i];
    }
#pragma unroll
    for (int o = 16; o; o >>= 1) {
        s += __shfl_xor_sync(0xffffffffu, s, o);
        ss += __shfl_xor_sync(0xffffffffu, ss, o);
    }
    float mean = s * (1.0f / Dq);
    float var = ss * (1.0f / Dq) - mean * mean;
    float rstd = rsqrtf(var + 1e-5f);
    float wn[8];
#pragma unroll
    for (int i = 0; i < 8; i++) wn[i] = (wv[i] - mean) * rstd * gs[lane + i * 32];
#pragma unroll
    for (int b = 0; b < Bq; b++) {
        float dot = 0.f;
#pragma unroll
        for (int i = 0; i < 8; i++) dot += wn[i] * xs[b * Dq + lane + i * 32];
#pragma unroll
        for (int o = 16; o; o >>= 1) dot += __shfl_xor_sync(0xffffffffu, dot, o);
        if (lane == 0) out[(size_t)b * Vq + v] = dot;
    }
}

// ---------------- launch ----------------
extern "C" void kernel_launch(void* const* d_in, const int* in_sizes, int n_in,
                              void* d_out, int out_size) {
    const int* tokens = (const int*)d_in[0];
    const float* wte = (const float*)d_in[1];
    const float* wpe = (const float*)d_in[2];
    const float* g_e = (const float*)d_in[3];
    const float* g_p = (const float*)d_in[4];
    const float* g_out = (const float*)d_in[5];
    const float* ff_w1 = (const float*)d_in[6];
    const float* ff_w2 = (const float*)d_in[7];
    const float* Wq = (const float*)d_in[8];
    const float* Wk = (const float*)d_in[9];
    const float* Wv = (const float*)d_in[10];
    float* out = (float*)d_out;

    constexpr int SM0 = 3 * (128 + 64) * 72 * 2;  // 82944 B
    cudaFuncSetAttribute(ffn_mma_kernel, cudaFuncAttributeMaxDynamicSharedMemorySize, SM0);

    // w1 transpose
    transpose_w1_kernel<<<256, dim3(32, 8)>>>(ff_w1);
    // 1. embeddings + positional LN (+ fused bf16 p_raw)
    embed_ln_kernel<<<(Bq * Sq + Sq) / 8, 256>>>(tokens, wte, wpe, g_e, g_p);
    // 2. FFN GEMM1 only: h = gelu(p0 @ W1)
    ffn_mma_kernel<<<dim3(Hq / 64, Sq / 128), 128, SM0>>>();
    // 3. p_last = p0[S-1] + h[S-1] @ W2 (64-way partials)
    plast_kernel<<<64, 256>>>(ff_w2);
    // 4. per-layer score direction m_l
    qk_q_kernel<<<dim3(Lq, 8), 256>>>(Wq);
    qk_m_kernel<<<dim3(Lq, 32), 256>>>(Wk);
    // 5. w2m_l = W2 @ m_l
    w2m_kernel<<<dim3(Hq / 8, Lq), 256>>>(ff_w2);
    // 6. scores -> exp (GEMM2 folded in via h . w2m)
    score_kernel<<<Sq / 8, 256>>>();
    // 7. ctx partials + chunk sums
    ctx_kernel<<<dim3(32, Bq), 256>>>();
    // 8. Wv projection (+ reduce + normalize)
    vproj_kernel<<<dim3(Lq, Bq), 256>>>(Wv);
    // 9. final LN
    final_ln_kernel<<<Bq, 256>>>(g_out);
    // 10. logits
    logits_kernel<<<Vq / 8, 256>>>(wte, g_e, out);
}